// round 5
// baseline (speedup 1.0000x reference)
#include <cuda_runtime.h>
#include <cuda_bf16.h>
#include <cstdint>

// Fixed problem shapes (SimpleGCN): N=50000 nodes, E=800000 edges,
// layers 256->256 (h1), 256->128 (h2), 128->128 (h3), out = [N, 512] fp32.
#define MAXN 50000
#define MAXE 800000
#define MPAD 50048

// ---------------- device scratch (static allocation; no cudaMalloc) --------
__device__ float          g_h[(size_t)MPAD * 256];   // GEMM output (max 256 cols)
__device__ __nv_bfloat16  g_ah[(size_t)MPAD * 256];  // A hi split
__device__ __nv_bfloat16  g_al[(size_t)MPAD * 256];  // A lo split
__device__ __nv_bfloat16  g_wth[256 * 256];          // W^T hi split [n][k]
__device__ __nv_bfloat16  g_wtl[256 * 256];          // W^T lo split [n][k]
__device__ float g_dinv[MAXN];
__device__ int   g_cnt[MAXN];
__device__ int   g_offs[MAXN + 1];
__device__ int   g_bsum[64];
__device__ int   g_esrc[MAXE];
__device__ float g_enorm[MAXE];
__device__ int   g_is64;

// ---------------- dtype detection -------------------------------------------
__global__ void k_detect(const int* __restrict__ ei32, int nwords) {
    __shared__ int any;
    if (threadIdx.x == 0) any = 0;
    __syncthreads();
    for (int i = threadIdx.x * 2 + 1; i < nwords; i += 2 * blockDim.x)
        if (ei32[i] != 0) any = 1;
    __syncthreads();
    if (threadIdx.x == 0) g_is64 = any ? 0 : 1;
}

__device__ __forceinline__ int load_idx(const int* p32, const long long* p64,
                                        int e, int n) {
    int v = g_is64 ? (int)p64[e] : p32[e];
    v = v < 0 ? 0 : (v >= n ? n - 1 : v);
    return v;
}

// ---------------- CSR construction ------------------------------------------
__global__ void k_zero_cnt(int n) {
    int i = blockIdx.x * blockDim.x + threadIdx.x;
    if (i < n) g_cnt[i] = 0;
}
__global__ void k_count(const int* __restrict__ d32,
                        const long long* __restrict__ d64, int E, int n) {
    int e = blockIdx.x * blockDim.x + threadIdx.x;
    if (e < E) atomicAdd(&g_cnt[load_idx(d32, d64, e, n)], 1);
}
__global__ void k_dinv(int n) {
    int i = blockIdx.x * blockDim.x + threadIdx.x;
    if (i < n) g_dinv[i] = rsqrtf((float)(g_cnt[i] + 1));
}
__global__ void k_scan_local(int n) {
    __shared__ int s[1024];
    int i = blockIdx.x * 1024 + threadIdx.x;
    int v = (i < n) ? g_cnt[i] : 0;
    s[threadIdx.x] = v;
    __syncthreads();
    for (int d = 1; d < 1024; d <<= 1) {
        int t = (threadIdx.x >= (unsigned)d) ? s[threadIdx.x - d] : 0;
        __syncthreads();
        s[threadIdx.x] += t;
        __syncthreads();
    }
    if (i < n) g_offs[i] = s[threadIdx.x] - v;
    if (threadIdx.x == 1023) g_bsum[blockIdx.x] = s[1023];
}
__global__ void k_scan_bsum(int nb, int n) {
    int run = 0;
    for (int b = 0; b < nb; b++) { int t = g_bsum[b]; g_bsum[b] = run; run += t; }
    g_offs[n] = run;
}
__global__ void k_scan_add(int n) {
    int i = blockIdx.x * 1024 + threadIdx.x;
    if (i < n) g_offs[i] += g_bsum[blockIdx.x];
}
__global__ void k_scatter(const int* __restrict__ s32,
                          const long long* __restrict__ s64,
                          const int* __restrict__ d32,
                          const long long* __restrict__ d64, int E, int n) {
    int e = blockIdx.x * blockDim.x + threadIdx.x;
    if (e >= E) return;
    int s = load_idx(s32, s64, e, n);
    int d = load_idx(d32, d64, e, n);
    int pos = g_offs[d] + atomicAdd(&g_cnt[d], 1);
    if (pos >= 0 && pos < MAXE) {
        g_esrc[pos]  = s;
        g_enorm[pos] = g_dinv[s] * g_dinv[d];
    }
}

// ---------------- bf16 split precompute --------------------------------------
__global__ void k_split_a(const float* __restrict__ src, int lda, int M, int K) {
    int i = blockIdx.x * blockDim.x + threadIdx.x;
    if (i >= MPAD * K) return;
    int row = i / K, col = i - row * K;
    float v = (row < M) ? src[(size_t)row * lda + col] : 0.f;
    __nv_bfloat16 h = __float2bfloat16(v);
    __nv_bfloat16 l = __float2bfloat16(v - __bfloat162float(h));
    g_ah[i] = h;
    g_al[i] = l;
}
__global__ void k_split_wt(const float* __restrict__ W, int K, int N) {
    int i = blockIdx.x * blockDim.x + threadIdx.x;
    if (i >= N * K) return;
    int n = i / K, k = i - n * K;
    float v = W[(size_t)k * N + n];
    __nv_bfloat16 h = __float2bfloat16(v);
    __nv_bfloat16 l = __float2bfloat16(v - __bfloat162float(h));
    g_wth[i] = h;
    g_wtl[i] = l;
}

// ---------------- warp-MMA bf16-split GEMM (cp.async pipelined) --------------
// C[M,N] = A @ W: A split in g_ah/g_al [MPAD,K], W^T split in g_wth/g_wtl [N,K].
// CTA tile 128x128, 8 warps (2M x 4N), warp tile 64x32 via m16n8k16, 3 terms.
#define ROWW 20                      // smem row stride (words): 32 bf16 + pad
#define ARR_B  (128 * ROWW * 4)      // 10240 B per array
#define BUF_B  (ARR_B * 4)           // AH AL BH BL per buffer

__device__ __forceinline__ void mma_bf16(float* c, uint32_t a0, uint32_t a1,
                                         uint32_t a2, uint32_t a3,
                                         uint32_t b0, uint32_t b1) {
    asm volatile(
        "mma.sync.aligned.m16n8k16.row.col.f32.bf16.bf16.f32 "
        "{%0,%1,%2,%3}, {%4,%5,%6,%7}, {%8,%9}, {%0,%1,%2,%3};"
        : "+f"(c[0]), "+f"(c[1]), "+f"(c[2]), "+f"(c[3])
        : "r"(a0), "r"(a1), "r"(a2), "r"(a3), "r"(b0), "r"(b1));
}
__device__ __forceinline__ void cp16(uint32_t dst, const void* src) {
    asm volatile("cp.async.cg.shared.global [%0], [%1], 16;"
                 :: "r"(dst), "l"(src));
}
__device__ __forceinline__ uint32_t smem_u32(const void* p) {
    uint32_t a;
    asm("{ .reg .u64 t; cvta.to.shared.u64 t, %1; cvt.u32.u64 %0, t; }"
        : "=r"(a) : "l"(p));
    return a;
}

__global__ void __launch_bounds__(256, 2)
k_gemm_mma(int M, int K, int N) {
    extern __shared__ char smem[];
    const uint32_t sbase = smem_u32(smem);

    const int tid  = threadIdx.x;
    const int lane = tid & 31;
    const int wid  = tid >> 5;
    const int wm   = wid & 1;
    const int wn   = wid >> 1;
    const int bm   = blockIdx.x * 128;
    const int bn   = blockIdx.y * 128;

    const int l4 = lane >> 2;
    const int l2 = (lane & 3) * 2;

    float acc[4][4][4];
#pragma unroll
    for (int i = 0; i < 4; i++)
#pragma unroll
        for (int j = 0; j < 4; j++)
#pragma unroll
            for (int k = 0; k < 4; k++) acc[i][j][k] = 0.f;

    // cp.async roles: 512 16B-chunks per array, 2 per thread
    const int c0r = tid >> 2, c0q = tid & 3;
    const int c1r = (tid + 256) >> 2, c1q = tid & 3;  // +256: q unchanged, row +64

    const __nv_bfloat16* srcs[4] = {g_ah, g_al, g_wth, g_wtl};
    const int rowbase[4] = {bm, bm, bn, bn};

    const int nStages = K >> 5;

    auto issue = [&](int st, int buf) {
        const int k0 = st << 5;
#pragma unroll
        for (int arr = 0; arr < 4; arr++) {
            const __nv_bfloat16* gp = srcs[arr];
            uint32_t db = sbase + buf * BUF_B + arr * ARR_B;
            cp16(db + (c0r * ROWW + c0q * 4) * 4,
                 gp + (size_t)(rowbase[arr] + c0r) * K + k0 + c0q * 8);
            cp16(db + (c1r * ROWW + c1q * 4) * 4,
                 gp + (size_t)(rowbase[arr] + c1r) * K + k0 + c1q * 8);
        }
        asm volatile("cp.async.commit_group;");
    };

    issue(0, 0);

    for (int st = 0; st < nStages; st++) {
        const int buf = st & 1;
        if (st + 1 < nStages) {
            issue(st + 1, buf ^ 1);
            asm volatile("cp.async.wait_group 1;");
        } else {
            asm volatile("cp.async.wait_group 0;");
        }
        __syncthreads();

        const uint32_t* sAh = (const uint32_t*)(smem + buf * BUF_B);
        const uint32_t* sAl = (const uint32_t*)(smem + buf * BUF_B + ARR_B);
        const uint32_t* sBh = (const uint32_t*)(smem + buf * BUF_B + 2 * ARR_B);
        const uint32_t* sBl = (const uint32_t*)(smem + buf * BUF_B + 3 * ARR_B);

#pragma unroll
        for (int ks = 0; ks < 2; ks++) {
            const int kwb = ks * 8 + (lane & 3);
            uint32_t bh[4][2], bl[4][2];
#pragma unroll
            for (int nt = 0; nt < 4; nt++) {
                int rw = (wn * 32 + nt * 8 + l4) * ROWW + kwb;
                bh[nt][0] = sBh[rw]; bh[nt][1] = sBh[rw + 4];
                bl[nt][0] = sBl[rw]; bl[nt][1] = sBl[rw + 4];
            }
#pragma unroll
            for (int mt = 0; mt < 4; mt++) {
                int r0 = (wm * 64 + mt * 16 + l4) * ROWW + kwb;
                int r1 = r0 + 8 * ROWW;
                uint32_t ah0 = sAh[r0], ah1 = sAh[r1];
                uint32_t ah2 = sAh[r0 + 4], ah3 = sAh[r1 + 4];
                uint32_t al0 = sAl[r0], al1 = sAl[r1];
                uint32_t al2 = sAl[r0 + 4], al3 = sAl[r1 + 4];
                // term-major order: no back-to-back RAW on same accumulator
#pragma unroll
                for (int nt = 0; nt < 4; nt++)
                    mma_bf16(acc[mt][nt], ah0, ah1, ah2, ah3, bh[nt][0], bh[nt][1]);
#pragma unroll
                for (int nt = 0; nt < 4; nt++)
                    mma_bf16(acc[mt][nt], ah0, ah1, ah2, ah3, bl[nt][0], bl[nt][1]);
#pragma unroll
                for (int nt = 0; nt < 4; nt++)
                    mma_bf16(acc[mt][nt], al0, al1, al2, al3, bh[nt][0], bh[nt][1]);
            }
        }
        __syncthreads();
    }

    // epilogue: fp32 float2 stores to g_h[M,N]
#pragma unroll
    for (int mt = 0; mt < 4; mt++) {
#pragma unroll
        for (int nt = 0; nt < 4; nt++) {
            int row = bm + wm * 64 + mt * 16 + l4;
            int col = bn + wn * 32 + nt * 8 + l2;
            if (row < M)
                *(float2*)&g_h[(size_t)row * N + col] =
                    make_float2(acc[mt][nt][0], acc[mt][nt][1]);
            if (row + 8 < M)
                *(float2*)&g_h[(size_t)(row + 8) * N + col] =
                    make_float2(acc[mt][nt][2], acc[mt][nt][3]);
        }
    }
}

// ---------------- aggregation: out[d] = relu(sum h[src]*norm + self + b) ----
template <int OC>
__global__ void k_agg(const float* __restrict__ bias,
                      float* __restrict__ out, int ldo) {
    int node = blockIdx.x;
    int c4   = threadIdx.x;                 // OC/4 threads
    float di = g_dinv[node];
    float s2 = di * di;
    float4 h0 = *(const float4*)&g_h[(size_t)node * OC + c4 * 4];
    float4 acc = make_float4(h0.x * s2, h0.y * s2, h0.z * s2, h0.w * s2);
    int beg = g_offs[node], end = g_offs[node + 1];
    for (int e = beg; e < end; e++) {
        int   s = g_esrc[e];
        float w = g_enorm[e];
        float4 hv = *(const float4*)&g_h[(size_t)s * OC + c4 * 4];
        acc.x += hv.x * w; acc.y += hv.y * w;
        acc.z += hv.z * w; acc.w += hv.w * w;
    }
    float4 b = *(const float4*)&bias[c4 * 4];
    float4 r;
    r.x = fmaxf(acc.x + b.x, 0.f);
    r.y = fmaxf(acc.y + b.y, 0.f);
    r.z = fmaxf(acc.z + b.z, 0.f);
    r.w = fmaxf(acc.w + b.w, 0.f);
    *(float4*)&out[(size_t)node * ldo + c4 * 4] = r;
}

// ---------------- host launcher ----------------------------------------------
extern "C" void kernel_launch(void* const* d_in, const int* in_sizes, int n_in,
                              void* d_out, int out_size) {
    const float* x  = (const float*)d_in[0];
    const int*       ei32 = (const int*)d_in[1];
    const long long* ei64 = (const long long*)d_in[1];
    const float* W1 = (const float*)d_in[2];
    const float* b1 = (const float*)d_in[3];
    const float* W2 = (const float*)d_in[4];
    const float* b2 = (const float*)d_in[5];
    const float* W3 = (const float*)d_in[6];
    const float* b3 = (const float*)d_in[7];
    float* out = (float*)d_out;

    int n = in_sizes[0] / 256;   // 50000
    int E = in_sizes[1] / 2;     // 800000

    const int SMEM = 2 * BUF_B;  // 81920
    cudaFuncSetAttribute(k_gemm_mma,
                         cudaFuncAttributeMaxDynamicSharedMemorySize, SMEM);

    k_detect<<<1, 256>>>(ei32, 4096);

    const int*       s32 = ei32;
    const int*       d32 = ei32 + E;
    const long long* s64 = ei64;
    const long long* d64 = ei64 + E;

    int nb = (n + 1023) / 1024;
    k_zero_cnt<<<(n + 255) / 256, 256>>>(n);
    k_count<<<(E + 255) / 256, 256>>>(d32, d64, E, n);
    k_dinv<<<(n + 255) / 256, 256>>>(n);
    k_scan_local<<<nb, 1024>>>(n);
    k_scan_bsum<<<1, 1>>>(nb, n);
    k_scan_add<<<nb, 1024>>>(n);
    k_zero_cnt<<<(n + 255) / 256, 256>>>(n);
    k_scatter<<<(E + 255) / 256, 256>>>(s32, s64, d32, d64, E, n);

    const int mtiles = (n + 127) / 128;  // 391

    // --- layer 1: 256 -> 256 ---
    k_split_a<<<(MPAD * 256 + 255) / 256, 256>>>(x, 256, n, 256);
    k_split_wt<<<(256 * 256 + 255) / 256, 256>>>(W1, 256, 256);
    k_gemm_mma<<<dim3(mtiles, 2), 256, SMEM>>>(n, 256, 256);
    k_agg<256><<<n, 64>>>(b1, out, 512);

    // --- layer 2: 256 -> 128 (input = out[:,0:256]) ---
    k_split_a<<<(MPAD * 256 + 255) / 256, 256>>>(out, 512, n, 256);
    k_split_wt<<<(128 * 256 + 255) / 256, 256>>>(W2, 256, 128);
    k_gemm_mma<<<dim3(mtiles, 1), 256, SMEM>>>(n, 256, 128);
    k_agg<128><<<n, 32>>>(b2, out + 256, 512);

    // --- layer 3: 128 -> 128 (input = out[:,256:384]) ---
    k_split_a<<<(MPAD * 128 + 255) / 256, 256>>>(out + 256, 512, n, 128);
    k_split_wt<<<(128 * 128 + 255) / 256, 256>>>(W3, 128, 128);
    k_gemm_mma<<<dim3(mtiles, 1), 256, SMEM>>>(n, 128, 128);
    k_agg<128><<<n, 32>>>(b3, out + 384, 512);
}

// round 6
// speedup vs baseline: 1.1903x; 1.1903x over previous
#include <cuda_runtime.h>
#include <cuda_bf16.h>
#include <cstdint>

// Fixed problem shapes (SimpleGCN): N=50000 nodes, E=800000 edges,
// layers 256->256 (h1), 256->128 (h2), 128->128 (h3), out = [N, 512] fp32.
#define MAXN 50000
#define MAXE 800000

// ---------------- device scratch (static allocation; no cudaMalloc) --------
__device__ float          g_h[(size_t)MAXN * 256];   // GEMM output (max 256 cols)
__device__ __nv_bfloat16  g_wth[256 * 256];          // W^T hi split [n][k]
__device__ __nv_bfloat16  g_wtl[256 * 256];          // W^T lo split [n][k]
__device__ float g_dinv[MAXN];
__device__ int   g_cnt[MAXN];
__device__ int   g_offs[MAXN + 1];
__device__ int   g_bsum[64];
__device__ int   g_esrc[MAXE];
__device__ float g_enorm[MAXE];
__device__ int   g_is64;

// ---------------- dtype detection -------------------------------------------
__global__ void k_detect(const int* __restrict__ ei32, int nwords) {
    __shared__ int any;
    if (threadIdx.x == 0) any = 0;
    __syncthreads();
    for (int i = threadIdx.x * 2 + 1; i < nwords; i += 2 * blockDim.x)
        if (ei32[i] != 0) any = 1;
    __syncthreads();
    if (threadIdx.x == 0) g_is64 = any ? 0 : 1;
}

__device__ __forceinline__ int load_idx(const int* p32, const long long* p64,
                                        int e, int n) {
    int v = g_is64 ? (int)p64[e] : p32[e];
    v = v < 0 ? 0 : (v >= n ? n - 1 : v);
    return v;
}

// ---------------- CSR construction ------------------------------------------
__global__ void k_zero_cnt(int n) {
    int i = blockIdx.x * blockDim.x + threadIdx.x;
    if (i < n) g_cnt[i] = 0;
}
__global__ void k_count(const int* __restrict__ d32,
                        const long long* __restrict__ d64, int E, int n) {
    int e = blockIdx.x * blockDim.x + threadIdx.x;
    if (e < E) atomicAdd(&g_cnt[load_idx(d32, d64, e, n)], 1);
}
__global__ void k_dinv(int n) {
    int i = blockIdx.x * blockDim.x + threadIdx.x;
    if (i < n) g_dinv[i] = rsqrtf((float)(g_cnt[i] + 1));
}
__global__ void k_scan_local(int n) {
    __shared__ int s[1024];
    int i = blockIdx.x * 1024 + threadIdx.x;
    int v = (i < n) ? g_cnt[i] : 0;
    s[threadIdx.x] = v;
    __syncthreads();
    for (int d = 1; d < 1024; d <<= 1) {
        int t = (threadIdx.x >= (unsigned)d) ? s[threadIdx.x - d] : 0;
        __syncthreads();
        s[threadIdx.x] += t;
        __syncthreads();
    }
    if (i < n) g_offs[i] = s[threadIdx.x] - v;
    if (threadIdx.x == 1023) g_bsum[blockIdx.x] = s[1023];
}
__global__ void k_scan_bsum(int nb, int n) {
    int run = 0;
    for (int b = 0; b < nb; b++) { int t = g_bsum[b]; g_bsum[b] = run; run += t; }
    g_offs[n] = run;
}
__global__ void k_scan_add(int n) {
    int i = blockIdx.x * 1024 + threadIdx.x;
    if (i < n) g_offs[i] += g_bsum[blockIdx.x];
}
__global__ void k_scatter(const int* __restrict__ s32,
                          const long long* __restrict__ s64,
                          const int* __restrict__ d32,
                          const long long* __restrict__ d64, int E, int n) {
    int e = blockIdx.x * blockDim.x + threadIdx.x;
    if (e >= E) return;
    int s = load_idx(s32, s64, e, n);
    int d = load_idx(d32, d64, e, n);
    int pos = g_offs[d] + atomicAdd(&g_cnt[d], 1);
    if (pos >= 0 && pos < MAXE) {
        g_esrc[pos]  = s;
        g_enorm[pos] = g_dinv[s] * g_dinv[d];
    }
}

// ---------------- W^T bf16 split precompute (tiny) ---------------------------
__global__ void k_split_wt(const float* __restrict__ W, int K, int N) {
    int i = blockIdx.x * blockDim.x + threadIdx.x;
    if (i >= N * K) return;
    int n = i / K, k = i - n * K;
    float v = W[(size_t)k * N + n];
    __nv_bfloat16 h = __float2bfloat16(v);
    __nv_bfloat16 l = __float2bfloat16(v - __bfloat162float(h));
    g_wth[i] = h;
    g_wtl[i] = l;
}

// ---------------- warp-MMA bf16-split GEMM (pipelined) -----------------------
// C[M,N] = A[M,K](fp32, lda) @ W[K,N] via precomputed W^T hi/lo.
// CTA tile 128x128, 8 warps (2M x 4N), warp tile 64x32 via m16n8k16, 3 terms.
// A: register-prefetch + in-kernel hi/lo split. B: cp.async double buffer.
#define ROWW 20                      // smem row stride (words)
#define ARR_B  (128 * ROWW * 4)      // 10240 B per array
#define BUF_B  (ARR_B * 4)           // AH AL BH BL per buffer

__device__ __forceinline__ void mma_bf16(float* c, uint32_t a0, uint32_t a1,
                                         uint32_t a2, uint32_t a3,
                                         uint32_t b0, uint32_t b1) {
    asm volatile(
        "mma.sync.aligned.m16n8k16.row.col.f32.bf16.bf16.f32 "
        "{%0,%1,%2,%3}, {%4,%5,%6,%7}, {%8,%9}, {%0,%1,%2,%3};"
        : "+f"(c[0]), "+f"(c[1]), "+f"(c[2]), "+f"(c[3])
        : "r"(a0), "r"(a1), "r"(a2), "r"(a3), "r"(b0), "r"(b1));
}
__device__ __forceinline__ void cp16(uint32_t dst, const void* src) {
    asm volatile("cp.async.cg.shared.global [%0], [%1], 16;"
                 :: "r"(dst), "l"(src));
}
__device__ __forceinline__ uint32_t smem_u32(const void* p) {
    uint32_t a;
    asm("{ .reg .u64 t; cvta.to.shared.u64 t, %1; cvt.u32.u64 %0, t; }"
        : "=r"(a) : "l"(p));
    return a;
}
// convert 16 fp32 -> bf16 hi/lo, store as 2x uint4 each into sh/sl
__device__ __forceinline__ void cvt_store16(uint32_t* sh, uint32_t* sl,
                                            int wordbase, const float* v) {
    uint32_t ph[8], pl[8];
#pragma unroll
    for (int i = 0; i < 8; i++) {
        __nv_bfloat16 h0 = __float2bfloat16(v[2 * i]);
        __nv_bfloat16 h1 = __float2bfloat16(v[2 * i + 1]);
        __nv_bfloat16 l0 = __float2bfloat16(v[2 * i] - __bfloat162float(h0));
        __nv_bfloat16 l1 = __float2bfloat16(v[2 * i + 1] - __bfloat162float(h1));
        ph[i] = (uint32_t)*(uint16_t*)&h0 | ((uint32_t)*(uint16_t*)&h1 << 16);
        pl[i] = (uint32_t)*(uint16_t*)&l0 | ((uint32_t)*(uint16_t*)&l1 << 16);
    }
    *(uint4*)&sh[wordbase]     = make_uint4(ph[0], ph[1], ph[2], ph[3]);
    *(uint4*)&sh[wordbase + 4] = make_uint4(ph[4], ph[5], ph[6], ph[7]);
    *(uint4*)&sl[wordbase]     = make_uint4(pl[0], pl[1], pl[2], pl[3]);
    *(uint4*)&sl[wordbase + 4] = make_uint4(pl[4], pl[5], pl[6], pl[7]);
}

__global__ void __launch_bounds__(256, 2)
k_gemm_mma(const float* __restrict__ A, int lda, int M, int K, int N) {
    extern __shared__ char smem[];
    const uint32_t sbase = smem_u32(smem);

    const int tid  = threadIdx.x;
    const int lane = tid & 31;
    const int wid  = tid >> 5;
    const int wm   = wid & 1;
    const int wn   = wid >> 1;
    const int bm   = blockIdx.x * 128;
    const int bn   = blockIdx.y * 128;

    const int l4 = lane >> 2;
    const int l2 = (lane & 3) * 2;

    float acc[4][4][4];
#pragma unroll
    for (int i = 0; i < 4; i++)
#pragma unroll
        for (int j = 0; j < 4; j++)
#pragma unroll
            for (int k = 0; k < 4; k++) acc[i][j][k] = 0.f;

    // A staging role: row 0..127, k-half 0/1 (16 consecutive k)
    const int ar = tid & 127, ah = tid >> 7;
    // B cp.async role: 2 chunks of 16B per thread per array
    const int c0r = tid >> 2, c0q = tid & 3;

    const int nStages = K >> 5;

    float av[16];
    auto ldA = [&](int st) {
        const int k0 = st << 5;
        const int grow = bm + ar;
        if (grow < M) {
            const float* p = &A[(size_t)grow * lda + k0 + ah * 16];
#pragma unroll
            for (int q = 0; q < 4; q++) {
                float4 f = *(const float4*)&p[q * 4];
                av[q * 4 + 0] = f.x; av[q * 4 + 1] = f.y;
                av[q * 4 + 2] = f.z; av[q * 4 + 3] = f.w;
            }
        } else {
#pragma unroll
            for (int q = 0; q < 16; q++) av[q] = 0.f;
        }
    };
    auto issueB = [&](int st, int buf) {
        const int k0 = st << 5;
        const uint32_t db = sbase + buf * BUF_B;
        const size_t g0 = (size_t)(bn + c0r) * K + k0 + c0q * 8;
        const size_t g1 = (size_t)(bn + c0r + 64) * K + k0 + c0q * 8;
        const uint32_t w0 = (c0r * ROWW + c0q * 4) * 4;
        const uint32_t w1 = ((c0r + 64) * ROWW + c0q * 4) * 4;
        cp16(db + 2 * ARR_B + w0, g_wth + g0);
        cp16(db + 2 * ARR_B + w1, g_wth + g1);
        cp16(db + 3 * ARR_B + w0, g_wtl + g0);
        cp16(db + 3 * ARR_B + w1, g_wtl + g1);
        asm volatile("cp.async.commit_group;");
    };

    ldA(0);
    issueB(0, 0);

    for (int st = 0; st < nStages; st++) {
        const int buf = st & 1;
        uint32_t* sAh = (uint32_t*)(smem + buf * BUF_B);
        uint32_t* sAl = (uint32_t*)(smem + buf * BUF_B + ARR_B);
        const uint32_t* sBh = (const uint32_t*)(smem + buf * BUF_B + 2 * ARR_B);
        const uint32_t* sBl = (const uint32_t*)(smem + buf * BUF_B + 3 * ARR_B);

        // stage A(st): convert prefetched regs, store to this buffer
        cvt_store16(sAh, sAl, ar * ROWW + ah * 8, av);

        asm volatile("cp.async.wait_group 0;");  // B(st) resident
        __syncthreads();

        // prefetch next stage: overlaps the MMA phase below
        if (st + 1 < nStages) {
            issueB(st + 1, buf ^ 1);   // safe: all warps passed sync
            ldA(st + 1);
        }

#pragma unroll
        for (int ks = 0; ks < 2; ks++) {
            const int kwb = ks * 8 + (lane & 3);
            uint32_t bh[4][2], bl[4][2];
#pragma unroll
            for (int nt = 0; nt < 4; nt++) {
                int rw = (wn * 32 + nt * 8 + l4) * ROWW + kwb;
                bh[nt][0] = sBh[rw]; bh[nt][1] = sBh[rw + 4];
                bl[nt][0] = sBl[rw]; bl[nt][1] = sBl[rw + 4];
            }
#pragma unroll
            for (int mt = 0; mt < 4; mt++) {
                int r0 = (wm * 64 + mt * 16 + l4) * ROWW + kwb;
                int r1 = r0 + 8 * ROWW;
                uint32_t ah0 = sAh[r0], ah1 = sAh[r1];
                uint32_t ah2 = sAh[r0 + 4], ah3 = sAh[r1 + 4];
                uint32_t al0 = sAl[r0], al1 = sAl[r1];
                uint32_t al2 = sAl[r0 + 4], al3 = sAl[r1 + 4];
#pragma unroll
                for (int nt = 0; nt < 4; nt++)
                    mma_bf16(acc[mt][nt], ah0, ah1, ah2, ah3, bh[nt][0], bh[nt][1]);
#pragma unroll
                for (int nt = 0; nt < 4; nt++)
                    mma_bf16(acc[mt][nt], ah0, ah1, ah2, ah3, bl[nt][0], bl[nt][1]);
#pragma unroll
                for (int nt = 0; nt < 4; nt++)
                    mma_bf16(acc[mt][nt], al0, al1, al2, al3, bh[nt][0], bh[nt][1]);
            }
        }
        // no trailing sync: next iteration writes the other buffer
    }

    // epilogue: fp32 float2 stores to g_h[M,N]
#pragma unroll
    for (int mt = 0; mt < 4; mt++) {
#pragma unroll
        for (int nt = 0; nt < 4; nt++) {
            int row = bm + wm * 64 + mt * 16 + l4;
            int col = bn + wn * 32 + nt * 8 + l2;
            if (row < M)
                *(float2*)&g_h[(size_t)row * N + col] =
                    make_float2(acc[mt][nt][0], acc[mt][nt][1]);
            if (row + 8 < M)
                *(float2*)&g_h[(size_t)(row + 8) * N + col] =
                    make_float2(acc[mt][nt][2], acc[mt][nt][3]);
        }
    }
}

// ---------------- aggregation: out[d] = relu(sum h[src]*norm + self + b) ----
template <int OC>
__global__ void k_agg(const float* __restrict__ bias,
                      float* __restrict__ out, int ldo) {
    int node = blockIdx.x;
    int c4   = threadIdx.x;                 // OC/4 threads
    float di = g_dinv[node];
    float s2 = di * di;
    float4 h0 = *(const float4*)&g_h[(size_t)node * OC + c4 * 4];
    float4 acc = make_float4(h0.x * s2, h0.y * s2, h0.z * s2, h0.w * s2);
    int beg = g_offs[node], end = g_offs[node + 1];
    int e = beg;
    for (; e + 1 < end; e += 2) {
        int   s0 = g_esrc[e],     s1 = g_esrc[e + 1];
        float w0 = g_enorm[e],    w1 = g_enorm[e + 1];
        float4 v0 = *(const float4*)&g_h[(size_t)s0 * OC + c4 * 4];
        float4 v1 = *(const float4*)&g_h[(size_t)s1 * OC + c4 * 4];
        acc.x += v0.x * w0 + v1.x * w1;
        acc.y += v0.y * w0 + v1.y * w1;
        acc.z += v0.z * w0 + v1.z * w1;
        acc.w += v0.w * w0 + v1.w * w1;
    }
    if (e < end) {
        int   s = g_esrc[e];
        float w = g_enorm[e];
        float4 hv = *(const float4*)&g_h[(size_t)s * OC + c4 * 4];
        acc.x += hv.x * w; acc.y += hv.y * w;
        acc.z += hv.z * w; acc.w += hv.w * w;
    }
    float4 b = *(const float4*)&bias[c4 * 4];
    float4 r;
    r.x = fmaxf(acc.x + b.x, 0.f);
    r.y = fmaxf(acc.y + b.y, 0.f);
    r.z = fmaxf(acc.z + b.z, 0.f);
    r.w = fmaxf(acc.w + b.w, 0.f);
    *(float4*)&out[(size_t)node * ldo + c4 * 4] = r;
}

// ---------------- host launcher ----------------------------------------------
extern "C" void kernel_launch(void* const* d_in, const int* in_sizes, int n_in,
                              void* d_out, int out_size) {
    const float* x  = (const float*)d_in[0];
    const int*       ei32 = (const int*)d_in[1];
    const long long* ei64 = (const long long*)d_in[1];
    const float* W1 = (const float*)d_in[2];
    const float* b1 = (const float*)d_in[3];
    const float* W2 = (const float*)d_in[4];
    const float* b2 = (const float*)d_in[5];
    const float* W3 = (const float*)d_in[6];
    const float* b3 = (const float*)d_in[7];
    float* out = (float*)d_out;

    int n = in_sizes[0] / 256;   // 50000
    int E = in_sizes[1] / 2;     // 800000

    const int SMEM = 2 * BUF_B;  // 81920
    cudaFuncSetAttribute(k_gemm_mma,
                         cudaFuncAttributeMaxDynamicSharedMemorySize, SMEM);

    k_detect<<<1, 256>>>(ei32, 4096);

    const int*       s32 = ei32;
    const int*       d32 = ei32 + E;
    const long long* s64 = ei64;
    const long long* d64 = ei64 + E;

    int nb = (n + 1023) / 1024;
    k_zero_cnt<<<(n + 255) / 256, 256>>>(n);
    k_count<<<(E + 255) / 256, 256>>>(d32, d64, E, n);
    k_dinv<<<(n + 255) / 256, 256>>>(n);
    k_scan_local<<<nb, 1024>>>(n);
    k_scan_bsum<<<1, 1>>>(nb, n);
    k_scan_add<<<nb, 1024>>>(n);
    k_zero_cnt<<<(n + 255) / 256, 256>>>(n);
    k_scatter<<<(E + 255) / 256, 256>>>(s32, s64, d32, d64, E, n);

    const int mtiles = (n + 127) / 128;  // 391

    // --- layer 1: 256 -> 256 ---
    k_split_wt<<<(256 * 256 + 255) / 256, 256>>>(W1, 256, 256);
    k_gemm_mma<<<dim3(mtiles, 2), 256, SMEM>>>(x, 256, n, 256, 256);
    k_agg<256><<<n, 64>>>(b1, out, 512);

    // --- layer 2: 256 -> 128 (input = out[:,0:256]) ---
    k_split_wt<<<(128 * 256 + 255) / 256, 256>>>(W2, 256, 128);
    k_gemm_mma<<<dim3(mtiles, 1), 256, SMEM>>>(out, 512, n, 256, 128);
    k_agg<128><<<n, 32>>>(b2, out + 256, 512);

    // --- layer 3: 128 -> 128 (input = out[:,256:384]) ---
    k_split_wt<<<(128 * 128 + 255) / 256, 256>>>(W3, 128, 128);
    k_gemm_mma<<<dim3(mtiles, 1), 256, SMEM>>>(out + 256, 512, n, 128, 128);
    k_agg<128><<<n, 32>>>(b3, out + 384, 512);
}

// round 7
// speedup vs baseline: 1.2993x; 1.0916x over previous
#include <cuda_runtime.h>
#include <cuda_bf16.h>
#include <cuda_fp16.h>
#include <cstdint>

// Fixed problem shapes (SimpleGCN): N=50000 nodes, E=800000 edges,
// layers 256->256 (h1), 256->128 (h2), 128->128 (h3), out = [N, 512] fp32.
#define MAXN 50000
#define MAXE 800000

// ---------------- device scratch (static allocation; no cudaMalloc) --------
__device__ __half         g_hh[(size_t)MAXN * 256];  // GEMM output, fp16
__device__ __nv_bfloat16  g_wth[256 * 256];          // W^T hi split [n][k]
__device__ __nv_bfloat16  g_wtl[256 * 256];          // W^T lo split [n][k]
__device__ float g_dinv[MAXN];
__device__ int   g_cnt[MAXN];
__device__ int   g_offs[MAXN + 1];
__device__ int   g_bsum[64];
__device__ int   g_esrc[MAXE];
__device__ float g_enorm[MAXE];
__device__ int   g_is64;

// ---------------- dtype detection -------------------------------------------
__global__ void k_detect(const int* __restrict__ ei32, int nwords) {
    __shared__ int any;
    if (threadIdx.x == 0) any = 0;
    __syncthreads();
    for (int i = threadIdx.x * 2 + 1; i < nwords; i += 2 * blockDim.x)
        if (ei32[i] != 0) any = 1;
    __syncthreads();
    if (threadIdx.x == 0) g_is64 = any ? 0 : 1;
}

__device__ __forceinline__ int load_idx(const int* p32, const long long* p64,
                                        int e, int n) {
    int v = g_is64 ? (int)p64[e] : p32[e];
    v = v < 0 ? 0 : (v >= n ? n - 1 : v);
    return v;
}

// ---------------- CSR construction ------------------------------------------
__global__ void k_zero_cnt(int n) {
    int i = blockIdx.x * blockDim.x + threadIdx.x;
    if (i < n) g_cnt[i] = 0;
}
__global__ void k_count(const int* __restrict__ d32,
                        const long long* __restrict__ d64, int E, int n) {
    int e = blockIdx.x * blockDim.x + threadIdx.x;
    if (e < E) atomicAdd(&g_cnt[load_idx(d32, d64, e, n)], 1);
}
__global__ void k_dinv(int n) {
    int i = blockIdx.x * blockDim.x + threadIdx.x;
    if (i < n) g_dinv[i] = rsqrtf((float)(g_cnt[i] + 1));
}
__global__ void k_scan_local(int n) {
    __shared__ int s[1024];
    int i = blockIdx.x * 1024 + threadIdx.x;
    int v = (i < n) ? g_cnt[i] : 0;
    s[threadIdx.x] = v;
    __syncthreads();
    for (int d = 1; d < 1024; d <<= 1) {
        int t = (threadIdx.x >= (unsigned)d) ? s[threadIdx.x - d] : 0;
        __syncthreads();
        s[threadIdx.x] += t;
        __syncthreads();
    }
    if (i < n) g_offs[i] = s[threadIdx.x] - v;
    if (threadIdx.x == 1023) g_bsum[blockIdx.x] = s[1023];
}
__global__ void k_scan_bsum(int nb, int n) {
    int run = 0;
    for (int b = 0; b < nb; b++) { int t = g_bsum[b]; g_bsum[b] = run; run += t; }
    g_offs[n] = run;
}
__global__ void k_scan_add(int n) {
    int i = blockIdx.x * 1024 + threadIdx.x;
    if (i < n) g_offs[i] += g_bsum[blockIdx.x];
}
__global__ void k_scatter(const int* __restrict__ s32,
                          const long long* __restrict__ s64,
                          const int* __restrict__ d32,
                          const long long* __restrict__ d64, int E, int n) {
    int e = blockIdx.x * blockDim.x + threadIdx.x;
    if (e >= E) return;
    int s = load_idx(s32, s64, e, n);
    int d = load_idx(d32, d64, e, n);
    int pos = g_offs[d] + atomicAdd(&g_cnt[d], 1);
    if (pos >= 0 && pos < MAXE) {
        g_esrc[pos]  = s;
        g_enorm[pos] = g_dinv[s] * g_dinv[d];
    }
}

// ---------------- W^T bf16 split precompute (tiny) ---------------------------
__global__ void k_split_wt(const float* __restrict__ W, int K, int N) {
    int i = blockIdx.x * blockDim.x + threadIdx.x;
    if (i >= N * K) return;
    int n = i / K, k = i - n * K;
    float v = W[(size_t)k * N + n];
    __nv_bfloat16 h = __float2bfloat16(v);
    __nv_bfloat16 l = __float2bfloat16(v - __bfloat162float(h));
    g_wth[i] = h;
    g_wtl[i] = l;
}

// ---------------- warp-MMA bf16-split GEMM (pipelined) -----------------------
// C[M,N] = A[M,K](fp32, lda) @ W[K,N] via precomputed W^T hi/lo. fp16 output.
// CTA tile 128x128, 8 warps (2M x 4N), warp tile 64x32 via m16n8k16, 3 terms.
#define ROWW 20
#define ARR_B  (128 * ROWW * 4)
#define BUF_B  (ARR_B * 4)

__device__ __forceinline__ void mma_bf16(float* c, uint32_t a0, uint32_t a1,
                                         uint32_t a2, uint32_t a3,
                                         uint32_t b0, uint32_t b1) {
    asm volatile(
        "mma.sync.aligned.m16n8k16.row.col.f32.bf16.bf16.f32 "
        "{%0,%1,%2,%3}, {%4,%5,%6,%7}, {%8,%9}, {%0,%1,%2,%3};"
        : "+f"(c[0]), "+f"(c[1]), "+f"(c[2]), "+f"(c[3])
        : "r"(a0), "r"(a1), "r"(a2), "r"(a3), "r"(b0), "r"(b1));
}
__device__ __forceinline__ void cp16(uint32_t dst, const void* src) {
    asm volatile("cp.async.cg.shared.global [%0], [%1], 16;"
                 :: "r"(dst), "l"(src));
}
__device__ __forceinline__ uint32_t smem_u32(const void* p) {
    uint32_t a;
    asm("{ .reg .u64 t; cvta.to.shared.u64 t, %1; cvt.u32.u64 %0, t; }"
        : "=r"(a) : "l"(p));
    return a;
}
__device__ __forceinline__ void cvt_store16(uint32_t* sh, uint32_t* sl,
                                            int wordbase, const float* v) {
    uint32_t ph[8], pl[8];
#pragma unroll
    for (int i = 0; i < 8; i++) {
        __nv_bfloat16 h0 = __float2bfloat16(v[2 * i]);
        __nv_bfloat16 h1 = __float2bfloat16(v[2 * i + 1]);
        __nv_bfloat16 l0 = __float2bfloat16(v[2 * i] - __bfloat162float(h0));
        __nv_bfloat16 l1 = __float2bfloat16(v[2 * i + 1] - __bfloat162float(h1));
        ph[i] = (uint32_t)*(uint16_t*)&h0 | ((uint32_t)*(uint16_t*)&h1 << 16);
        pl[i] = (uint32_t)*(uint16_t*)&l0 | ((uint32_t)*(uint16_t*)&l1 << 16);
    }
    *(uint4*)&sh[wordbase]     = make_uint4(ph[0], ph[1], ph[2], ph[3]);
    *(uint4*)&sh[wordbase + 4] = make_uint4(ph[4], ph[5], ph[6], ph[7]);
    *(uint4*)&sl[wordbase]     = make_uint4(pl[0], pl[1], pl[2], pl[3]);
    *(uint4*)&sl[wordbase + 4] = make_uint4(pl[4], pl[5], pl[6], pl[7]);
}

__global__ void __launch_bounds__(256, 2)
k_gemm_mma(const float* __restrict__ A, int lda, int M, int K, int N) {
    extern __shared__ char smem[];
    const uint32_t sbase = smem_u32(smem);

    const int tid  = threadIdx.x;
    const int lane = tid & 31;
    const int wid  = tid >> 5;
    const int wm   = wid & 1;
    const int wn   = wid >> 1;
    const int bm   = blockIdx.x * 128;
    const int bn   = blockIdx.y * 128;

    const int l4 = lane >> 2;
    const int l2 = (lane & 3) * 2;

    float acc[4][4][4];
#pragma unroll
    for (int i = 0; i < 4; i++)
#pragma unroll
        for (int j = 0; j < 4; j++)
#pragma unroll
            for (int k = 0; k < 4; k++) acc[i][j][k] = 0.f;

    const int ar = tid & 127, ah = tid >> 7;
    const int c0r = tid >> 2, c0q = tid & 3;

    const int nStages = K >> 5;

    float av[16];
    auto ldA = [&](int st) {
        const int k0 = st << 5;
        const int grow = bm + ar;
        if (grow < M) {
            const float* p = &A[(size_t)grow * lda + k0 + ah * 16];
#pragma unroll
            for (int q = 0; q < 4; q++) {
                float4 f = *(const float4*)&p[q * 4];
                av[q * 4 + 0] = f.x; av[q * 4 + 1] = f.y;
                av[q * 4 + 2] = f.z; av[q * 4 + 3] = f.w;
            }
        } else {
#pragma unroll
            for (int q = 0; q < 16; q++) av[q] = 0.f;
        }
    };
    auto issueB = [&](int st, int buf) {
        const int k0 = st << 5;
        const uint32_t db = sbase + buf * BUF_B;
        const size_t g0 = (size_t)(bn + c0r) * K + k0 + c0q * 8;
        const size_t g1 = (size_t)(bn + c0r + 64) * K + k0 + c0q * 8;
        const uint32_t w0 = (c0r * ROWW + c0q * 4) * 4;
        const uint32_t w1 = ((c0r + 64) * ROWW + c0q * 4) * 4;
        cp16(db + 2 * ARR_B + w0, g_wth + g0);
        cp16(db + 2 * ARR_B + w1, g_wth + g1);
        cp16(db + 3 * ARR_B + w0, g_wtl + g0);
        cp16(db + 3 * ARR_B + w1, g_wtl + g1);
        asm volatile("cp.async.commit_group;");
    };

    ldA(0);
    issueB(0, 0);

    for (int st = 0; st < nStages; st++) {
        const int buf = st & 1;
        uint32_t* sAh = (uint32_t*)(smem + buf * BUF_B);
        uint32_t* sAl = (uint32_t*)(smem + buf * BUF_B + ARR_B);
        const uint32_t* sBh = (const uint32_t*)(smem + buf * BUF_B + 2 * ARR_B);
        const uint32_t* sBl = (const uint32_t*)(smem + buf * BUF_B + 3 * ARR_B);

        cvt_store16(sAh, sAl, ar * ROWW + ah * 8, av);

        asm volatile("cp.async.wait_group 0;");
        __syncthreads();

        if (st + 1 < nStages) {
            issueB(st + 1, buf ^ 1);
            ldA(st + 1);
        }

#pragma unroll
        for (int ks = 0; ks < 2; ks++) {
            const int kwb = ks * 8 + (lane & 3);
            uint32_t bh[4][2], bl[4][2];
#pragma unroll
            for (int nt = 0; nt < 4; nt++) {
                int rw = (wn * 32 + nt * 8 + l4) * ROWW + kwb;
                bh[nt][0] = sBh[rw]; bh[nt][1] = sBh[rw + 4];
                bl[nt][0] = sBl[rw]; bl[nt][1] = sBl[rw + 4];
            }
#pragma unroll
            for (int mt = 0; mt < 4; mt++) {
                int r0 = (wm * 64 + mt * 16 + l4) * ROWW + kwb;
                int r1 = r0 + 8 * ROWW;
                uint32_t ah0 = sAh[r0], ah1 = sAh[r1];
                uint32_t ah2 = sAh[r0 + 4], ah3 = sAh[r1 + 4];
                uint32_t al0 = sAl[r0], al1 = sAl[r1];
                uint32_t al2 = sAl[r0 + 4], al3 = sAl[r1 + 4];
#pragma unroll
                for (int nt = 0; nt < 4; nt++)
                    mma_bf16(acc[mt][nt], ah0, ah1, ah2, ah3, bh[nt][0], bh[nt][1]);
#pragma unroll
                for (int nt = 0; nt < 4; nt++)
                    mma_bf16(acc[mt][nt], ah0, ah1, ah2, ah3, bl[nt][0], bl[nt][1]);
#pragma unroll
                for (int nt = 0; nt < 4; nt++)
                    mma_bf16(acc[mt][nt], al0, al1, al2, al3, bh[nt][0], bh[nt][1]);
            }
        }
    }

    // epilogue: fp16 half2 stores to g_hh[M,N]
#pragma unroll
    for (int mt = 0; mt < 4; mt++) {
#pragma unroll
        for (int nt = 0; nt < 4; nt++) {
            int row = bm + wm * 64 + mt * 16 + l4;
            int col = bn + wn * 32 + nt * 8 + l2;
            if (row < M)
                *(__half2*)&g_hh[(size_t)row * N + col] =
                    __floats2half2_rn(acc[mt][nt][0], acc[mt][nt][1]);
            if (row + 8 < M)
                *(__half2*)&g_hh[(size_t)(row + 8) * N + col] =
                    __floats2half2_rn(acc[mt][nt][2], acc[mt][nt][3]);
        }
    }
}

// ---------------- aggregation (fp16 gathers) ----------------------------------
__device__ __forceinline__ void unpack8(uint4 v, float* f) {
    float2 a = __half22float2(*(__half2*)&v.x);
    float2 b = __half22float2(*(__half2*)&v.y);
    float2 c = __half22float2(*(__half2*)&v.z);
    float2 d = __half22float2(*(__half2*)&v.w);
    f[0] = a.x; f[1] = a.y; f[2] = b.x; f[3] = b.y;
    f[4] = c.x; f[5] = c.y; f[6] = d.x; f[7] = d.y;
}

// NPB nodes per block; OC/8 threads per node, 8 cols (16B) per thread.
template <int OC, int NPB>
__global__ void k_agg(const float* __restrict__ bias,
                      float* __restrict__ out, int ldo, int n) {
    int node = blockIdx.x * NPB + threadIdx.y;
    if (node >= n) return;
    const int colb = threadIdx.x * 8;

    float di = g_dinv[node];
    float s2 = di * di;

    float acc[8], f[8];
    uint4 hs = *(const uint4*)&g_hh[(size_t)node * OC + colb];
    unpack8(hs, f);
#pragma unroll
    for (int j = 0; j < 8; j++) acc[j] = f[j] * s2;

    int beg = g_offs[node], end = g_offs[node + 1];
    int e = beg;
    for (; e + 1 < end; e += 2) {
        int   s0 = g_esrc[e],  s1 = g_esrc[e + 1];
        float w0 = g_enorm[e], w1 = g_enorm[e + 1];
        uint4 v0 = *(const uint4*)&g_hh[(size_t)s0 * OC + colb];
        uint4 v1 = *(const uint4*)&g_hh[(size_t)s1 * OC + colb];
        float f0[8], f1[8];
        unpack8(v0, f0);
        unpack8(v1, f1);
#pragma unroll
        for (int j = 0; j < 8; j++) acc[j] += f0[j] * w0 + f1[j] * w1;
    }
    if (e < end) {
        int   s = g_esrc[e];
        float w = g_enorm[e];
        uint4 v = *(const uint4*)&g_hh[(size_t)s * OC + colb];
        unpack8(v, f);
#pragma unroll
        for (int j = 0; j < 8; j++) acc[j] += f[j] * w;
    }

    float4 b0 = *(const float4*)&bias[colb];
    float4 b1 = *(const float4*)&bias[colb + 4];
    float* op = &out[(size_t)node * ldo + colb];
    *(float4*)op = make_float4(fmaxf(acc[0] + b0.x, 0.f),
                               fmaxf(acc[1] + b0.y, 0.f),
                               fmaxf(acc[2] + b0.z, 0.f),
                               fmaxf(acc[3] + b0.w, 0.f));
    *(float4*)(op + 4) = make_float4(fmaxf(acc[4] + b1.x, 0.f),
                                     fmaxf(acc[5] + b1.y, 0.f),
                                     fmaxf(acc[6] + b1.z, 0.f),
                                     fmaxf(acc[7] + b1.w, 0.f));
}

// ---------------- host launcher ----------------------------------------------
extern "C" void kernel_launch(void* const* d_in, const int* in_sizes, int n_in,
                              void* d_out, int out_size) {
    const float* x  = (const float*)d_in[0];
    const int*       ei32 = (const int*)d_in[1];
    const long long* ei64 = (const long long*)d_in[1];
    const float* W1 = (const float*)d_in[2];
    const float* b1 = (const float*)d_in[3];
    const float* W2 = (const float*)d_in[4];
    const float* b2 = (const float*)d_in[5];
    const float* W3 = (const float*)d_in[6];
    const float* b3 = (const float*)d_in[7];
    float* out = (float*)d_out;

    int n = in_sizes[0] / 256;   // 50000
    int E = in_sizes[1] / 2;     // 800000

    const int SMEM = 2 * BUF_B;  // 81920
    cudaFuncSetAttribute(k_gemm_mma,
                         cudaFuncAttributeMaxDynamicSharedMemorySize, SMEM);

    k_detect<<<1, 256>>>(ei32, 4096);

    const int*       s32 = ei32;
    const int*       d32 = ei32 + E;
    const long long* s64 = ei64;
    const long long* d64 = ei64 + E;

    int nb = (n + 1023) / 1024;
    k_zero_cnt<<<(n + 255) / 256, 256>>>(n);
    k_count<<<(E + 255) / 256, 256>>>(d32, d64, E, n);
    k_dinv<<<(n + 255) / 256, 256>>>(n);
    k_scan_local<<<nb, 1024>>>(n);
    k_scan_bsum<<<1, 1>>>(nb, n);
    k_scan_add<<<nb, 1024>>>(n);
    k_zero_cnt<<<(n + 255) / 256, 256>>>(n);
    k_scatter<<<(E + 255) / 256, 256>>>(s32, s64, d32, d64, E, n);

    const int mtiles = (n + 127) / 128;  // 391

    // --- layer 1: 256 -> 256 ---
    k_split_wt<<<(256 * 256 + 255) / 256, 256>>>(W1, 256, 256);
    k_gemm_mma<<<dim3(mtiles, 2), 256, SMEM>>>(x, 256, n, 256, 256);
    k_agg<256, 8><<<(n + 7) / 8, dim3(32, 8)>>>(b1, out, 512, n);

    // --- layer 2: 256 -> 128 (input = out[:,0:256]) ---
    k_split_wt<<<(128 * 256 + 255) / 256, 256>>>(W2, 256, 128);
    k_gemm_mma<<<dim3(mtiles, 1), 256, SMEM>>>(out, 512, n, 256, 128);
    k_agg<128, 16><<<(n + 15) / 16, dim3(16, 16)>>>(b2, out + 256, 512, n);

    // --- layer 3: 128 -> 128 (input = out[:,256:384]) ---
    k_split_wt<<<(128 * 128 + 255) / 256, 256>>>(W3, 128, 128);
    k_gemm_mma<<<dim3(mtiles, 1), 256, SMEM>>>(out + 256, 512, n, 128, 128);
    k_agg<128, 16><<<(n + 15) / 16, dim3(16, 16)>>>(b3, out + 384, 512, n);
}

// round 9
// speedup vs baseline: 1.4278x; 1.0989x over previous
#include <cuda_runtime.h>
#include <cuda_bf16.h>
#include <cuda_fp16.h>
#include <cstdint>

// Fixed problem shapes (SimpleGCN): N=50000 nodes, E=800000 edges,
// layers 256->256 (h1), 256->128 (h2), 128->128 (h3), out = [N, 512] fp32.
#define MAXN 50000
#define MAXE 800000
#define MPAD 50048

// ---------------- device scratch (static allocation; no cudaMalloc) --------
__device__ __half         g_hh[(size_t)MPAD * 256];  // GEMM output, fp16
__device__ __half         g_a16[(size_t)MPAD * 256]; // agg output fp16 (GEMM A in)
__device__ __nv_bfloat16  g_wth[256 * 256];          // W^T hi split bf16 [n][k]
__device__ __nv_bfloat16  g_wtl[256 * 256];          // W^T lo split bf16 [n][k]
__device__ __half         g_wth16[256 * 256];        // W^T hi split fp16 [n][k]
__device__ __half         g_wtl16[256 * 256];        // W^T lo split fp16 [n][k]
__device__ float g_dinv[MAXN];
__device__ int   g_cnt[MAXN];
__device__ int   g_offs[MAXN + 1];
__device__ int   g_bsum[64];
__device__ int   g_esrc[MAXE];
__device__ float g_enorm[MAXE];
__device__ int   g_is64;

// ---------------- dtype detection -------------------------------------------
__global__ void k_detect(const int* __restrict__ ei32, int nwords) {
    __shared__ int any;
    if (threadIdx.x == 0) any = 0;
    __syncthreads();
    for (int i = threadIdx.x * 2 + 1; i < nwords; i += 2 * blockDim.x)
        if (ei32[i] != 0) any = 1;
    __syncthreads();
    if (threadIdx.x == 0) g_is64 = any ? 0 : 1;
}

__device__ __forceinline__ int load_idx(const int* p32, const long long* p64,
                                        int e, int n) {
    int v = g_is64 ? (int)p64[e] : p32[e];
    v = v < 0 ? 0 : (v >= n ? n - 1 : v);
    return v;
}

// ---------------- CSR construction ------------------------------------------
__global__ void k_zero_cnt(int n) {
    int i = blockIdx.x * blockDim.x + threadIdx.x;
    if (i < n) g_cnt[i] = 0;
}
__global__ void k_count(const int* __restrict__ d32,
                        const long long* __restrict__ d64, int E, int n) {
    int e = blockIdx.x * blockDim.x + threadIdx.x;
    if (e < E) atomicAdd(&g_cnt[load_idx(d32, d64, e, n)], 1);
}
__global__ void k_dinv(int n) {
    int i = blockIdx.x * blockDim.x + threadIdx.x;
    if (i < n) g_dinv[i] = rsqrtf((float)(g_cnt[i] + 1));
}
__global__ void k_scan_local(int n) {
    __shared__ int s[1024];
    int i = blockIdx.x * 1024 + threadIdx.x;
    int v = (i < n) ? g_cnt[i] : 0;
    s[threadIdx.x] = v;
    __syncthreads();
    for (int d = 1; d < 1024; d <<= 1) {
        int t = (threadIdx.x >= (unsigned)d) ? s[threadIdx.x - d] : 0;
        __syncthreads();
        s[threadIdx.x] += t;
        __syncthreads();
    }
    if (i < n) g_offs[i] = s[threadIdx.x] - v;
    if (threadIdx.x == 1023) g_bsum[blockIdx.x] = s[1023];
}
__global__ void k_scan_bsum(int nb, int n) {
    int run = 0;
    for (int b = 0; b < nb; b++) { int t = g_bsum[b]; g_bsum[b] = run; run += t; }
    g_offs[n] = run;
}
__global__ void k_scan_add(int n) {
    int i = blockIdx.x * 1024 + threadIdx.x;
    if (i < n) g_offs[i] += g_bsum[blockIdx.x];
}
__global__ void k_scatter(const int* __restrict__ s32,
                          const long long* __restrict__ s64,
                          const int* __restrict__ d32,
                          const long long* __restrict__ d64, int E, int n) {
    int e = blockIdx.x * blockDim.x + threadIdx.x;
    if (e >= E) return;
    int s = load_idx(s32, s64, e, n);
    int d = load_idx(d32, d64, e, n);
    int pos = g_offs[d] + atomicAdd(&g_cnt[d], 1);
    if (pos >= 0 && pos < MAXE) {
        g_esrc[pos]  = s;
        g_enorm[pos] = g_dinv[s] * g_dinv[d];
    }
}

// ---------------- W^T split precompute (tiny) ---------------------------------
__global__ void k_split_wt(const float* __restrict__ W, int K, int N) {
    int i = blockIdx.x * blockDim.x + threadIdx.x;
    if (i >= N * K) return;
    int n = i / K, k = i - n * K;
    float v = W[(size_t)k * N + n];
    __nv_bfloat16 h = __float2bfloat16(v);
    __nv_bfloat16 l = __float2bfloat16(v - __bfloat162float(h));
    g_wth[i] = h;
    g_wtl[i] = l;
}
__global__ void k_split_wt16(const float* __restrict__ W, int K, int N) {
    int i = blockIdx.x * blockDim.x + threadIdx.x;
    if (i >= N * K) return;
    int n = i / K, k = i - n * K;
    float v = W[(size_t)k * N + n];
    __half h = __float2half_rn(v);
    __half l = __float2half_rn(v - __half2float(h));
    g_wth16[i] = h;
    g_wtl16[i] = l;
}

// ---------------- common PTX helpers ------------------------------------------
#define ROWW 20
#define ARR_B  (128 * ROWW * 4)

__device__ __forceinline__ void mma_bf16(float* c, uint32_t a0, uint32_t a1,
                                         uint32_t a2, uint32_t a3,
                                         uint32_t b0, uint32_t b1) {
    asm volatile(
        "mma.sync.aligned.m16n8k16.row.col.f32.bf16.bf16.f32 "
        "{%0,%1,%2,%3}, {%4,%5,%6,%7}, {%8,%9}, {%0,%1,%2,%3};"
        : "+f"(c[0]), "+f"(c[1]), "+f"(c[2]), "+f"(c[3])
        : "r"(a0), "r"(a1), "r"(a2), "r"(a3), "r"(b0), "r"(b1));
}
__device__ __forceinline__ void mma_f16(float* c, uint32_t a0, uint32_t a1,
                                        uint32_t a2, uint32_t a3,
                                        uint32_t b0, uint32_t b1) {
    asm volatile(
        "mma.sync.aligned.m16n8k16.row.col.f32.f16.f16.f32 "
        "{%0,%1,%2,%3}, {%4,%5,%6,%7}, {%8,%9}, {%0,%1,%2,%3};"
        : "+f"(c[0]), "+f"(c[1]), "+f"(c[2]), "+f"(c[3])
        : "r"(a0), "r"(a1), "r"(a2), "r"(a3), "r"(b0), "r"(b1));
}
__device__ __forceinline__ void cp16(uint32_t dst, const void* src) {
    asm volatile("cp.async.cg.shared.global [%0], [%1], 16;"
                 :: "r"(dst), "l"(src));
}
__device__ __forceinline__ uint32_t smem_u32(const void* p) {
    uint32_t a;
    asm("{ .reg .u64 t; cvta.to.shared.u64 t, %1; cvt.u32.u64 %0, t; }"
        : "=r"(a) : "l"(p));
    return a;
}
__device__ __forceinline__ void cvt_store16(uint32_t* sh, uint32_t* sl,
                                            int wordbase, const float* v) {
    uint32_t ph[8], pl[8];
#pragma unroll
    for (int i = 0; i < 8; i++) {
        __nv_bfloat16 h0 = __float2bfloat16(v[2 * i]);
        __nv_bfloat16 h1 = __float2bfloat16(v[2 * i + 1]);
        __nv_bfloat16 l0 = __float2bfloat16(v[2 * i] - __bfloat162float(h0));
        __nv_bfloat16 l1 = __float2bfloat16(v[2 * i + 1] - __bfloat162float(h1));
        ph[i] = (uint32_t)*(uint16_t*)&h0 | ((uint32_t)*(uint16_t*)&h1 << 16);
        pl[i] = (uint32_t)*(uint16_t*)&l0 | ((uint32_t)*(uint16_t*)&l1 << 16);
    }
    *(uint4*)&sh[wordbase]     = make_uint4(ph[0], ph[1], ph[2], ph[3]);
    *(uint4*)&sh[wordbase + 4] = make_uint4(ph[4], ph[5], ph[6], ph[7]);
    *(uint4*)&sl[wordbase]     = make_uint4(pl[0], pl[1], pl[2], pl[3]);
    *(uint4*)&sl[wordbase + 4] = make_uint4(pl[4], pl[5], pl[6], pl[7]);
}

// ---------------- GEMM 1: fp32 A, 3-term bf16 split (layer 1) ----------------
#define BUF_B  (ARR_B * 4)

__global__ void __launch_bounds__(256, 2)
k_gemm_mma(const float* __restrict__ A, int lda, int M, int K, int N) {
    extern __shared__ char smem[];
    const uint32_t sbase = smem_u32(smem);

    const int tid  = threadIdx.x;
    const int lane = tid & 31;
    const int wid  = tid >> 5;
    const int wm   = wid & 1;
    const int wn   = wid >> 1;
    const int bm   = blockIdx.x * 128;
    const int bn   = blockIdx.y * 128;

    const int l4 = lane >> 2;
    const int l2 = (lane & 3) * 2;

    float acc[4][4][4];
#pragma unroll
    for (int i = 0; i < 4; i++)
#pragma unroll
        for (int j = 0; j < 4; j++)
#pragma unroll
            for (int k = 0; k < 4; k++) acc[i][j][k] = 0.f;

    const int ar = tid & 127, ah = tid >> 7;
    const int c0r = tid >> 2, c0q = tid & 3;

    const int nStages = K >> 5;

    float av[16];
    auto ldA = [&](int st) {
        const int k0 = st << 5;
        const int grow = bm + ar;
        if (grow < M) {
            const float* p = &A[(size_t)grow * lda + k0 + ah * 16];
#pragma unroll
            for (int q = 0; q < 4; q++) {
                float4 f = *(const float4*)&p[q * 4];
                av[q * 4 + 0] = f.x; av[q * 4 + 1] = f.y;
                av[q * 4 + 2] = f.z; av[q * 4 + 3] = f.w;
            }
        } else {
#pragma unroll
            for (int q = 0; q < 16; q++) av[q] = 0.f;
        }
    };
    auto issueB = [&](int st, int buf) {
        const int k0 = st << 5;
        const uint32_t db = sbase + buf * BUF_B;
        const size_t g0 = (size_t)(bn + c0r) * K + k0 + c0q * 8;
        const size_t g1 = (size_t)(bn + c0r + 64) * K + k0 + c0q * 8;
        const uint32_t w0 = (c0r * ROWW + c0q * 4) * 4;
        const uint32_t w1 = ((c0r + 64) * ROWW + c0q * 4) * 4;
        cp16(db + 2 * ARR_B + w0, g_wth + g0);
        cp16(db + 2 * ARR_B + w1, g_wth + g1);
        cp16(db + 3 * ARR_B + w0, g_wtl + g0);
        cp16(db + 3 * ARR_B + w1, g_wtl + g1);
        asm volatile("cp.async.commit_group;");
    };

    ldA(0);
    issueB(0, 0);

    for (int st = 0; st < nStages; st++) {
        const int buf = st & 1;
        uint32_t* sAh = (uint32_t*)(smem + buf * BUF_B);
        uint32_t* sAl = (uint32_t*)(smem + buf * BUF_B + ARR_B);
        const uint32_t* sBh = (const uint32_t*)(smem + buf * BUF_B + 2 * ARR_B);
        const uint32_t* sBl = (const uint32_t*)(smem + buf * BUF_B + 3 * ARR_B);

        cvt_store16(sAh, sAl, ar * ROWW + ah * 8, av);

        asm volatile("cp.async.wait_group 0;");
        __syncthreads();

        if (st + 1 < nStages) {
            issueB(st + 1, buf ^ 1);
            ldA(st + 1);
        }

#pragma unroll
        for (int ks = 0; ks < 2; ks++) {
            const int kwb = ks * 8 + (lane & 3);
            uint32_t bh[4][2], bl[4][2];
#pragma unroll
            for (int nt = 0; nt < 4; nt++) {
                int rw = (wn * 32 + nt * 8 + l4) * ROWW + kwb;
                bh[nt][0] = sBh[rw]; bh[nt][1] = sBh[rw + 4];
                bl[nt][0] = sBl[rw]; bl[nt][1] = sBl[rw + 4];
            }
#pragma unroll
            for (int mt = 0; mt < 4; mt++) {
                int r0 = (wm * 64 + mt * 16 + l4) * ROWW + kwb;
                int r1 = r0 + 8 * ROWW;
                uint32_t ah0 = sAh[r0], ah1 = sAh[r1];
                uint32_t ah2 = sAh[r0 + 4], ah3 = sAh[r1 + 4];
                uint32_t al0 = sAl[r0], al1 = sAl[r1];
                uint32_t al2 = sAl[r0 + 4], al3 = sAl[r1 + 4];
#pragma unroll
                for (int nt = 0; nt < 4; nt++)
                    mma_bf16(acc[mt][nt], ah0, ah1, ah2, ah3, bh[nt][0], bh[nt][1]);
#pragma unroll
                for (int nt = 0; nt < 4; nt++)
                    mma_bf16(acc[mt][nt], ah0, ah1, ah2, ah3, bl[nt][0], bl[nt][1]);
#pragma unroll
                for (int nt = 0; nt < 4; nt++)
                    mma_bf16(acc[mt][nt], al0, al1, al2, al3, bh[nt][0], bh[nt][1]);
            }
        }
    }

#pragma unroll
    for (int mt = 0; mt < 4; mt++) {
#pragma unroll
        for (int nt = 0; nt < 4; nt++) {
            int row = bm + wm * 64 + mt * 16 + l4;
            int col = bn + wn * 32 + nt * 8 + l2;
            if (row < M)
                *(__half2*)&g_hh[(size_t)row * N + col] =
                    __floats2half2_rn(acc[mt][nt][0], acc[mt][nt][1]);
            if (row + 8 < M)
                *(__half2*)&g_hh[(size_t)(row + 8) * N + col] =
                    __floats2half2_rn(acc[mt][nt][2], acc[mt][nt][3]);
        }
    }
}

// ---------------- GEMM 2: fp16 A = g_a16 (exact), 2-term fp16 W (layers 2,3) -
// NOTE: reads g_a16 directly (device global). Do NOT pass device globals as
// kernel args from host code — that binds the host shadow symbol (round-8 bug).
#define BUF_B2 (ARR_B * 3)

__global__ void __launch_bounds__(256, 2)
k_gemm_f16(int M, int K, int N) {
    extern __shared__ char smem[];
    const uint32_t sbase = smem_u32(smem);
    const __half* A = g_a16;           // lda = 256, device-side binding
    const int lda = 256;

    const int tid  = threadIdx.x;
    const int lane = tid & 31;
    const int wid  = tid >> 5;
    const int wm   = wid & 1;
    const int wn   = wid >> 1;
    const int bm   = blockIdx.x * 128;
    const int bn   = blockIdx.y * 128;

    const int l4 = lane >> 2;
    const int l2 = (lane & 3) * 2;

    float acc[4][4][4];
#pragma unroll
    for (int i = 0; i < 4; i++)
#pragma unroll
        for (int j = 0; j < 4; j++)
#pragma unroll
            for (int k = 0; k < 4; k++) acc[i][j][k] = 0.f;

    const int c0r = tid >> 2, c0q = tid & 3;
    const int nStages = K >> 5;

    // A rows bm..bm+127 may exceed M but stay < MPAD (g_a16 padded): safe.
    auto issue = [&](int st, int buf) {
        const int k0 = st << 5;
        const uint32_t db = sbase + buf * BUF_B2;
        const uint32_t w0 = (c0r * ROWW + c0q * 4) * 4;
        const uint32_t w1 = ((c0r + 64) * ROWW + c0q * 4) * 4;
        const size_t a0 = (size_t)(bm + c0r) * lda + k0 + c0q * 8;
        const size_t a1 = (size_t)(bm + c0r + 64) * lda + k0 + c0q * 8;
        cp16(db + w0, A + a0);
        cp16(db + w1, A + a1);
        const size_t g0 = (size_t)(bn + c0r) * K + k0 + c0q * 8;
        const size_t g1 = (size_t)(bn + c0r + 64) * K + k0 + c0q * 8;
        cp16(db + ARR_B + w0, g_wth16 + g0);
        cp16(db + ARR_B + w1, g_wth16 + g1);
        cp16(db + 2 * ARR_B + w0, g_wtl16 + g0);
        cp16(db + 2 * ARR_B + w1, g_wtl16 + g1);
        asm volatile("cp.async.commit_group;");
    };

    issue(0, 0);

    for (int st = 0; st < nStages; st++) {
        const int buf = st & 1;
        if (st + 1 < nStages) {
            issue(st + 1, buf ^ 1);
            asm volatile("cp.async.wait_group 1;");
        } else {
            asm volatile("cp.async.wait_group 0;");
        }
        __syncthreads();

        const uint32_t* sA  = (const uint32_t*)(smem + buf * BUF_B2);
        const uint32_t* sBh = (const uint32_t*)(smem + buf * BUF_B2 + ARR_B);
        const uint32_t* sBl = (const uint32_t*)(smem + buf * BUF_B2 + 2 * ARR_B);

#pragma unroll
        for (int ks = 0; ks < 2; ks++) {
            const int kwb = ks * 8 + (lane & 3);
            uint32_t bh[4][2], bl[4][2];
#pragma unroll
            for (int nt = 0; nt < 4; nt++) {
                int rw = (wn * 32 + nt * 8 + l4) * ROWW + kwb;
                bh[nt][0] = sBh[rw]; bh[nt][1] = sBh[rw + 4];
                bl[nt][0] = sBl[rw]; bl[nt][1] = sBl[rw + 4];
            }
#pragma unroll
            for (int mt = 0; mt < 4; mt++) {
                int r0 = (wm * 64 + mt * 16 + l4) * ROWW + kwb;
                int r1 = r0 + 8 * ROWW;
                uint32_t a0 = sA[r0], a1 = sA[r1];
                uint32_t a2 = sA[r0 + 4], a3 = sA[r1 + 4];
#pragma unroll
                for (int nt = 0; nt < 4; nt++)
                    mma_f16(acc[mt][nt], a0, a1, a2, a3, bh[nt][0], bh[nt][1]);
#pragma unroll
                for (int nt = 0; nt < 4; nt++)
                    mma_f16(acc[mt][nt], a0, a1, a2, a3, bl[nt][0], bl[nt][1]);
            }
        }
        __syncthreads();
    }

#pragma unroll
    for (int mt = 0; mt < 4; mt++) {
#pragma unroll
        for (int nt = 0; nt < 4; nt++) {
            int row = bm + wm * 64 + mt * 16 + l4;
            int col = bn + wn * 32 + nt * 8 + l2;
            if (row < M)
                *(__half2*)&g_hh[(size_t)row * N + col] =
                    __floats2half2_rn(acc[mt][nt][0], acc[mt][nt][1]);
            if (row + 8 < M)
                *(__half2*)&g_hh[(size_t)(row + 8) * N + col] =
                    __floats2half2_rn(acc[mt][nt][2], acc[mt][nt][3]);
        }
    }
}

// ---------------- aggregation (fp16 gathers) ----------------------------------
__device__ __forceinline__ void unpack8(uint4 v, float* f) {
    float2 a = __half22float2(*(__half2*)&v.x);
    float2 b = __half22float2(*(__half2*)&v.y);
    float2 c = __half22float2(*(__half2*)&v.z);
    float2 d = __half22float2(*(__half2*)&v.w);
    f[0] = a.x; f[1] = a.y; f[2] = b.x; f[3] = b.y;
    f[4] = c.x; f[5] = c.y; f[6] = d.x; f[7] = d.y;
}

// NPB nodes per block; OC/8 threads per node. W16: also write fp16 copy to g_a16.
template <int OC, int NPB, bool W16>
__global__ void k_agg(const float* __restrict__ bias,
                      float* __restrict__ out, int ldo, int n) {
    int node = blockIdx.x * NPB + threadIdx.y;
    if (node >= n) return;
    const int colb = threadIdx.x * 8;

    float di = g_dinv[node];
    float s2 = di * di;

    float acc[8], f[8];
    uint4 hs = *(const uint4*)&g_hh[(size_t)node * OC + colb];
    unpack8(hs, f);
#pragma unroll
    for (int j = 0; j < 8; j++) acc[j] = f[j] * s2;

    int beg = g_offs[node], end = g_offs[node + 1];
    int e = beg;
    for (; e + 1 < end; e += 2) {
        int   s0 = g_esrc[e],  s1 = g_esrc[e + 1];
        float w0 = g_enorm[e], w1 = g_enorm[e + 1];
        uint4 v0 = *(const uint4*)&g_hh[(size_t)s0 * OC + colb];
        uint4 v1 = *(const uint4*)&g_hh[(size_t)s1 * OC + colb];
        float f0[8], f1[8];
        unpack8(v0, f0);
        unpack8(v1, f1);
#pragma unroll
        for (int j = 0; j < 8; j++) acc[j] += f0[j] * w0 + f1[j] * w1;
    }
    if (e < end) {
        int   s = g_esrc[e];
        float w = g_enorm[e];
        uint4 v = *(const uint4*)&g_hh[(size_t)s * OC + colb];
        unpack8(v, f);
#pragma unroll
        for (int j = 0; j < 8; j++) acc[j] += f[j] * w;
    }

    float4 b0 = *(const float4*)&bias[colb];
    float4 b1 = *(const float4*)&bias[colb + 4];
    float r[8];
    r[0] = fmaxf(acc[0] + b0.x, 0.f); r[1] = fmaxf(acc[1] + b0.y, 0.f);
    r[2] = fmaxf(acc[2] + b0.z, 0.f); r[3] = fmaxf(acc[3] + b0.w, 0.f);
    r[4] = fmaxf(acc[4] + b1.x, 0.f); r[5] = fmaxf(acc[5] + b1.y, 0.f);
    r[6] = fmaxf(acc[6] + b1.z, 0.f); r[7] = fmaxf(acc[7] + b1.w, 0.f);

    float* op = &out[(size_t)node * ldo + colb];
    *(float4*)op       = make_float4(r[0], r[1], r[2], r[3]);
    *(float4*)(op + 4) = make_float4(r[4], r[5], r[6], r[7]);

    if (W16) {
        uint4 hv;
        __half2 p0 = __floats2half2_rn(r[0], r[1]);
        __half2 p1 = __floats2half2_rn(r[2], r[3]);
        __half2 p2 = __floats2half2_rn(r[4], r[5]);
        __half2 p3 = __floats2half2_rn(r[6], r[7]);
        hv.x = *(uint32_t*)&p0; hv.y = *(uint32_t*)&p1;
        hv.z = *(uint32_t*)&p2; hv.w = *(uint32_t*)&p3;
        *(uint4*)&g_a16[(size_t)node * 256 + colb] = hv;
    }
}

// ---------------- host launcher ----------------------------------------------
extern "C" void kernel_launch(void* const* d_in, const int* in_sizes, int n_in,
                              void* d_out, int out_size) {
    const float* x  = (const float*)d_in[0];
    const int*       ei32 = (const int*)d_in[1];
    const long long* ei64 = (const long long*)d_in[1];
    const float* W1 = (const float*)d_in[2];
    const float* b1 = (const float*)d_in[3];
    const float* W2 = (const float*)d_in[4];
    const float* b2 = (const float*)d_in[5];
    const float* W3 = (const float*)d_in[6];
    const float* b3 = (const float*)d_in[7];
    float* out = (float*)d_out;

    int n = in_sizes[0] / 256;   // 50000
    int E = in_sizes[1] / 2;     // 800000

    const int SMEM1 = 2 * BUF_B;   // 81920
    const int SMEM2 = 2 * BUF_B2;  // 61440
    cudaFuncSetAttribute(k_gemm_mma,
                         cudaFuncAttributeMaxDynamicSharedMemorySize, SMEM1);
    cudaFuncSetAttribute(k_gemm_f16,
                         cudaFuncAttributeMaxDynamicSharedMemorySize, SMEM2);

    k_detect<<<1, 256>>>(ei32, 4096);

    const int*       s32 = ei32;
    const int*       d32 = ei32 + E;
    const long long* s64 = ei64;
    const long long* d64 = ei64 + E;

    int nb = (n + 1023) / 1024;
    k_zero_cnt<<<(n + 255) / 256, 256>>>(n);
    k_count<<<(E + 255) / 256, 256>>>(d32, d64, E, n);
    k_dinv<<<(n + 255) / 256, 256>>>(n);
    k_scan_local<<<nb, 1024>>>(n);
    k_scan_bsum<<<1, 1>>>(nb, n);
    k_scan_add<<<nb, 1024>>>(n);
    k_zero_cnt<<<(n + 255) / 256, 256>>>(n);
    k_scatter<<<(E + 255) / 256, 256>>>(s32, s64, d32, d64, E, n);

    const int mtiles = (n + 127) / 128;  // 391

    // --- layer 1: 256 -> 256 (fp32 x, 3-term bf16) ---
    k_split_wt<<<(256 * 256 + 255) / 256, 256>>>(W1, 256, 256);
    k_gemm_mma<<<dim3(mtiles, 2), 256, SMEM1>>>(x, 256, n, 256, 256);
    k_agg<256, 8, true><<<(n + 7) / 8, dim3(32, 8)>>>(b1, out, 512, n);

    // --- layer 2: 256 -> 128 (fp16 h1 exact, 2-term fp16) ---
    k_split_wt16<<<(128 * 256 + 255) / 256, 256>>>(W2, 256, 128);
    k_gemm_f16<<<dim3(mtiles, 1), 256, SMEM2>>>(n, 256, 128);
    k_agg<128, 16, true><<<(n + 15) / 16, dim3(16, 16)>>>(b2, out + 256, 512, n);

    // --- layer 3: 128 -> 128 (fp16 h2 exact, 2-term fp16) ---
    k_split_wt16<<<(128 * 128 + 255) / 256, 256>>>(W3, 128, 128);
    k_gemm_f16<<<dim3(mtiles, 1), 256, SMEM2>>>(n, 128, 128);
    k_agg<128, 16, false><<<(n + 15) / 16, dim3(16, 16)>>>(b3, out + 384, 512, n);
}

// round 10
// speedup vs baseline: 1.6000x; 1.1206x over previous
#include <cuda_runtime.h>
#include <cuda_fp16.h>
#include <cstdint>

// Fixed problem shapes (SimpleGCN): N=50000 nodes, E=800000 edges,
// layers 256->256 (h1), 256->128 (h2), 128->128 (h3), out = [N, 512] fp32.
#define MAXN 50000
#define MAXE 800000
#define MPAD 50048

// ---------------- device scratch (static allocation; no cudaMalloc) --------
__device__ __half g_hh[(size_t)MPAD * 256];   // GEMM output, fp16
__device__ __half g_a16[(size_t)MPAD * 256];  // GEMM A input, fp16 (x16 / agg out)
__device__ __half g_wth16[256 * 256];         // W^T hi split fp16 [n][k]
__device__ __half g_wtl16[256 * 256];         // W^T lo split fp16 [n][k]
__device__ float g_dinv[MAXN];
__device__ int   g_cnt[MAXN];
__device__ int   g_offs[MAXN + 1];
__device__ int   g_bsum[64];
__device__ int   g_esrc[MAXE];
__device__ float g_enorm[MAXE];
__device__ int   g_is64;

// ---------------- dtype detection -------------------------------------------
__global__ void k_detect(const int* __restrict__ ei32, int nwords) {
    __shared__ int any;
    if (threadIdx.x == 0) any = 0;
    __syncthreads();
    for (int i = threadIdx.x * 2 + 1; i < nwords; i += 2 * blockDim.x)
        if (ei32[i] != 0) any = 1;
    __syncthreads();
    if (threadIdx.x == 0) g_is64 = any ? 0 : 1;
}

__device__ __forceinline__ int load_idx(const int* p32, const long long* p64,
                                        int e, int n) {
    int v = g_is64 ? (int)p64[e] : p32[e];
    v = v < 0 ? 0 : (v >= n ? n - 1 : v);
    return v;
}

// ---------------- CSR construction ------------------------------------------
__global__ void k_zero_cnt(int n) {
    int i = blockIdx.x * blockDim.x + threadIdx.x;
    if (i < n) g_cnt[i] = 0;
}
__global__ void k_count(const int* __restrict__ d32,
                        const long long* __restrict__ d64, int E, int n) {
    int e = blockIdx.x * blockDim.x + threadIdx.x;
    if (e < E) atomicAdd(&g_cnt[load_idx(d32, d64, e, n)], 1);
}
__global__ void k_dinv(int n) {
    int i = blockIdx.x * blockDim.x + threadIdx.x;
    if (i < n) g_dinv[i] = rsqrtf((float)(g_cnt[i] + 1));
}
__global__ void k_scan_local(int n) {
    __shared__ int s[1024];
    int i = blockIdx.x * 1024 + threadIdx.x;
    int v = (i < n) ? g_cnt[i] : 0;
    s[threadIdx.x] = v;
    __syncthreads();
    for (int d = 1; d < 1024; d <<= 1) {
        int t = (threadIdx.x >= (unsigned)d) ? s[threadIdx.x - d] : 0;
        __syncthreads();
        s[threadIdx.x] += t;
        __syncthreads();
    }
    if (i < n) g_offs[i] = s[threadIdx.x] - v;
    if (threadIdx.x == 1023) g_bsum[blockIdx.x] = s[1023];
}
// parallel scan of block sums (nb <= 64) — replaces the serial 1-thread scan
__global__ void k_scan_bsum(int nb) {
    __shared__ int s[64];
    int t = threadIdx.x;
    int v = (t < nb) ? g_bsum[t] : 0;
    s[t] = v;
    __syncthreads();
    for (int d = 1; d < 64; d <<= 1) {
        int x = (t >= d) ? s[t - d] : 0;
        __syncthreads();
        s[t] += x;
        __syncthreads();
    }
    if (t < nb) g_bsum[t] = s[t] - v;  // exclusive
}
__global__ void k_scan_add(int n) {
    int i = blockIdx.x * 1024 + threadIdx.x;
    if (i < n) g_offs[i] += g_bsum[blockIdx.x];
}
// scatter bumps g_offs[d] directly: afterwards g_offs[d] = END of node d.
// Consumers read beg = (d ? g_offs[d-1] : 0), end = g_offs[d].
__global__ void k_scatter(const int* __restrict__ s32,
                          const long long* __restrict__ s64,
                          const int* __restrict__ d32,
                          const long long* __restrict__ d64, int E, int n) {
    int e = blockIdx.x * blockDim.x + threadIdx.x;
    if (e >= E) return;
    int s = load_idx(s32, s64, e, n);
    int d = load_idx(d32, d64, e, n);
    int pos = atomicAdd(&g_offs[d], 1);
    if (pos >= 0 && pos < MAXE) {
        g_esrc[pos]  = s;
        g_enorm[pos] = g_dinv[s] * g_dinv[d];
    }
}

// ---------------- x -> fp16 (once) + W^T fp16 split (tiny) -------------------
__global__ void k_x16(const float* __restrict__ x, int M) {
    int i = blockIdx.x * blockDim.x + threadIdx.x;   // one per 8 elems
    if (i >= MPAD * 32) return;
    int row = i >> 5, q = i & 31;
    uint4 hv = make_uint4(0, 0, 0, 0);
    if (row < M) {
        const float* p = &x[(size_t)row * 256 + q * 8];
        float4 f0 = *(const float4*)p;
        float4 f1 = *(const float4*)(p + 4);
        __half2 p0 = __floats2half2_rn(f0.x, f0.y);
        __half2 p1 = __floats2half2_rn(f0.z, f0.w);
        __half2 p2 = __floats2half2_rn(f1.x, f1.y);
        __half2 p3 = __floats2half2_rn(f1.z, f1.w);
        hv.x = *(uint32_t*)&p0; hv.y = *(uint32_t*)&p1;
        hv.z = *(uint32_t*)&p2; hv.w = *(uint32_t*)&p3;
    }
    *(uint4*)&g_a16[(size_t)row * 256 + q * 8] = hv;
}
__global__ void k_split_wt16(const float* __restrict__ W, int K, int N) {
    int i = blockIdx.x * blockDim.x + threadIdx.x;
    if (i >= N * K) return;
    int n = i / K, k = i - n * K;
    float v = W[(size_t)k * N + n];
    __half h = __float2half_rn(v);
    __half l = __float2half_rn(v - __half2float(h));
    g_wth16[i] = h;
    g_wtl16[i] = l;
}

// ---------------- fp16 2-term warp-MMA GEMM (cp.async pipelined) -------------
// C[M,N] = A(g_a16)[M,256-stride] @ W[K,N]: W^T hi/lo fp16 in g_wth16/g_wtl16.
// CTA tile 128x128, 8 warps (2M x 4N), warp tile 64x32 via m16n8k16.
#define ROWW 20
#define ARR_B  (128 * ROWW * 4)
#define BUF_B2 (ARR_B * 3)

__device__ __forceinline__ void mma_f16(float* c, uint32_t a0, uint32_t a1,
                                        uint32_t a2, uint32_t a3,
                                        uint32_t b0, uint32_t b1) {
    asm volatile(
        "mma.sync.aligned.m16n8k16.row.col.f32.f16.f16.f32 "
        "{%0,%1,%2,%3}, {%4,%5,%6,%7}, {%8,%9}, {%0,%1,%2,%3};"
        : "+f"(c[0]), "+f"(c[1]), "+f"(c[2]), "+f"(c[3])
        : "r"(a0), "r"(a1), "r"(a2), "r"(a3), "r"(b0), "r"(b1));
}
__device__ __forceinline__ void cp16(uint32_t dst, const void* src) {
    asm volatile("cp.async.cg.shared.global [%0], [%1], 16;"
                 :: "r"(dst), "l"(src));
}
__device__ __forceinline__ uint32_t smem_u32(const void* p) {
    uint32_t a;
    asm("{ .reg .u64 t; cvta.to.shared.u64 t, %1; cvt.u32.u64 %0, t; }"
        : "=r"(a) : "l"(p));
    return a;
}

__global__ void __launch_bounds__(256, 2)
k_gemm_f16(int M, int K, int N) {
    extern __shared__ char smem[];
    const uint32_t sbase = smem_u32(smem);
    const __half* A = g_a16;            // device-side binding; lda = 256
    const int lda = 256;

    const int tid  = threadIdx.x;
    const int lane = tid & 31;
    const int wid  = tid >> 5;
    const int wm   = wid & 1;
    const int wn   = wid >> 1;
    const int bm   = blockIdx.x * 128;
    const int bn   = blockIdx.y * 128;

    const int l4 = lane >> 2;
    const int l2 = (lane & 3) * 2;

    float acc[4][4][4];
#pragma unroll
    for (int i = 0; i < 4; i++)
#pragma unroll
        for (int j = 0; j < 4; j++)
#pragma unroll
            for (int k = 0; k < 4; k++) acc[i][j][k] = 0.f;

    const int c0r = tid >> 2, c0q = tid & 3;
    const int nStages = K >> 5;

    // A rows bm..bm+127 may exceed M but stay < MPAD (g_a16 padded): safe.
    auto issue = [&](int st, int buf) {
        const int k0 = st << 5;
        const uint32_t db = sbase + buf * BUF_B2;
        const uint32_t w0 = (c0r * ROWW + c0q * 4) * 4;
        const uint32_t w1 = ((c0r + 64) * ROWW + c0q * 4) * 4;
        const size_t a0 = (size_t)(bm + c0r) * lda + k0 + c0q * 8;
        const size_t a1 = (size_t)(bm + c0r + 64) * lda + k0 + c0q * 8;
        cp16(db + w0, A + a0);
        cp16(db + w1, A + a1);
        const size_t g0 = (size_t)(bn + c0r) * K + k0 + c0q * 8;
        const size_t g1 = (size_t)(bn + c0r + 64) * K + k0 + c0q * 8;
        cp16(db + ARR_B + w0, g_wth16 + g0);
        cp16(db + ARR_B + w1, g_wth16 + g1);
        cp16(db + 2 * ARR_B + w0, g_wtl16 + g0);
        cp16(db + 2 * ARR_B + w1, g_wtl16 + g1);
        asm volatile("cp.async.commit_group;");
    };

    issue(0, 0);

    for (int st = 0; st < nStages; st++) {
        const int buf = st & 1;
        if (st + 1 < nStages) {
            issue(st + 1, buf ^ 1);
            asm volatile("cp.async.wait_group 1;");
        } else {
            asm volatile("cp.async.wait_group 0;");
        }
        __syncthreads();

        const uint32_t* sA  = (const uint32_t*)(smem + buf * BUF_B2);
        const uint32_t* sBh = (const uint32_t*)(smem + buf * BUF_B2 + ARR_B);
        const uint32_t* sBl = (const uint32_t*)(smem + buf * BUF_B2 + 2 * ARR_B);

#pragma unroll
        for (int ks = 0; ks < 2; ks++) {
            const int kwb = ks * 8 + (lane & 3);
            uint32_t bh[4][2], bl[4][2];
#pragma unroll
            for (int nt = 0; nt < 4; nt++) {
                int rw = (wn * 32 + nt * 8 + l4) * ROWW + kwb;
                bh[nt][0] = sBh[rw]; bh[nt][1] = sBh[rw + 4];
                bl[nt][0] = sBl[rw]; bl[nt][1] = sBl[rw + 4];
            }
#pragma unroll
            for (int mt = 0; mt < 4; mt++) {
                int r0 = (wm * 64 + mt * 16 + l4) * ROWW + kwb;
                int r1 = r0 + 8 * ROWW;
                uint32_t a0 = sA[r0], a1 = sA[r1];
                uint32_t a2 = sA[r0 + 4], a3 = sA[r1 + 4];
#pragma unroll
                for (int nt = 0; nt < 4; nt++)
                    mma_f16(acc[mt][nt], a0, a1, a2, a3, bh[nt][0], bh[nt][1]);
#pragma unroll
                for (int nt = 0; nt < 4; nt++)
                    mma_f16(acc[mt][nt], a0, a1, a2, a3, bl[nt][0], bl[nt][1]);
            }
        }
        __syncthreads();
    }

#pragma unroll
    for (int mt = 0; mt < 4; mt++) {
#pragma unroll
        for (int nt = 0; nt < 4; nt++) {
            int row = bm + wm * 64 + mt * 16 + l4;
            int col = bn + wn * 32 + nt * 8 + l2;
            if (row < M)
                *(__half2*)&g_hh[(size_t)row * N + col] =
                    __floats2half2_rn(acc[mt][nt][0], acc[mt][nt][1]);
            if (row + 8 < M)
                *(__half2*)&g_hh[(size_t)(row + 8) * N + col] =
                    __floats2half2_rn(acc[mt][nt][2], acc[mt][nt][3]);
        }
    }
}

// ---------------- aggregation (fp16 gathers) ----------------------------------
__device__ __forceinline__ void unpack8(uint4 v, float* f) {
    float2 a = __half22float2(*(__half2*)&v.x);
    float2 b = __half22float2(*(__half2*)&v.y);
    float2 c = __half22float2(*(__half2*)&v.z);
    float2 d = __half22float2(*(__half2*)&v.w);
    f[0] = a.x; f[1] = a.y; f[2] = b.x; f[3] = b.y;
    f[4] = c.x; f[5] = c.y; f[6] = d.x; f[7] = d.y;
}

// NPB nodes per block; OC/8 threads per node. W16: also write fp16 copy to g_a16.
// g_offs holds END positions (post-scatter); beg = node ? offs[node-1] : 0.
template <int OC, int NPB, bool W16>
__global__ void k_agg(const float* __restrict__ bias,
                      float* __restrict__ out, int ldo, int n) {
    int node = blockIdx.x * NPB + threadIdx.y;
    if (node >= n) return;
    const int colb = threadIdx.x * 8;

    float di = g_dinv[node];
    float s2 = di * di;

    float acc[8], f[8];
    uint4 hs = *(const uint4*)&g_hh[(size_t)node * OC + colb];
    unpack8(hs, f);
#pragma unroll
    for (int j = 0; j < 8; j++) acc[j] = f[j] * s2;

    int beg = node ? g_offs[node - 1] : 0;
    int end = g_offs[node];
    int e = beg;
    for (; e + 1 < end; e += 2) {
        int   s0 = g_esrc[e],  s1 = g_esrc[e + 1];
        float w0 = g_enorm[e], w1 = g_enorm[e + 1];
        uint4 v0 = *(const uint4*)&g_hh[(size_t)s0 * OC + colb];
        uint4 v1 = *(const uint4*)&g_hh[(size_t)s1 * OC + colb];
        float f0[8], f1[8];
        unpack8(v0, f0);
        unpack8(v1, f1);
#pragma unroll
        for (int j = 0; j < 8; j++) acc[j] += f0[j] * w0 + f1[j] * w1;
    }
    if (e < end) {
        int   s = g_esrc[e];
        float w = g_enorm[e];
        uint4 v = *(const uint4*)&g_hh[(size_t)s * OC + colb];
        unpack8(v, f);
#pragma unroll
        for (int j = 0; j < 8; j++) acc[j] += f[j] * w;
    }

    float4 b0 = *(const float4*)&bias[colb];
    float4 b1 = *(const float4*)&bias[colb + 4];
    float r[8];
    r[0] = fmaxf(acc[0] + b0.x, 0.f); r[1] = fmaxf(acc[1] + b0.y, 0.f);
    r[2] = fmaxf(acc[2] + b0.z, 0.f); r[3] = fmaxf(acc[3] + b0.w, 0.f);
    r[4] = fmaxf(acc[4] + b1.x, 0.f); r[5] = fmaxf(acc[5] + b1.y, 0.f);
    r[6] = fmaxf(acc[6] + b1.z, 0.f); r[7] = fmaxf(acc[7] + b1.w, 0.f);

    float* op = &out[(size_t)node * ldo + colb];
    *(float4*)op       = make_float4(r[0], r[1], r[2], r[3]);
    *(float4*)(op + 4) = make_float4(r[4], r[5], r[6], r[7]);

    if (W16) {
        uint4 hv;
        __half2 p0 = __floats2half2_rn(r[0], r[1]);
        __half2 p1 = __floats2half2_rn(r[2], r[3]);
        __half2 p2 = __floats2half2_rn(r[4], r[5]);
        __half2 p3 = __floats2half2_rn(r[6], r[7]);
        hv.x = *(uint32_t*)&p0; hv.y = *(uint32_t*)&p1;
        hv.z = *(uint32_t*)&p2; hv.w = *(uint32_t*)&p3;
        *(uint4*)&g_a16[(size_t)node * 256 + colb] = hv;
    }
}

// ---------------- host launcher ----------------------------------------------
extern "C" void kernel_launch(void* const* d_in, const int* in_sizes, int n_in,
                              void* d_out, int out_size) {
    const float* x  = (const float*)d_in[0];
    const int*       ei32 = (const int*)d_in[1];
    const long long* ei64 = (const long long*)d_in[1];
    const float* W1 = (const float*)d_in[2];
    const float* b1 = (const float*)d_in[3];
    const float* W2 = (const float*)d_in[4];
    const float* b2 = (const float*)d_in[5];
    const float* W3 = (const float*)d_in[6];
    const float* b3 = (const float*)d_in[7];
    float* out = (float*)d_out;

    int n = in_sizes[0] / 256;   // 50000
    int E = in_sizes[1] / 2;     // 800000

    const int SMEM2 = 2 * BUF_B2;  // 61440
    cudaFuncSetAttribute(k_gemm_f16,
                         cudaFuncAttributeMaxDynamicSharedMemorySize, SMEM2);

    k_detect<<<1, 256>>>(ei32, 4096);

    const int*       s32 = ei32;
    const int*       d32 = ei32 + E;
    const long long* s64 = ei64;
    const long long* d64 = ei64 + E;

    int nb = (n + 1023) / 1024;  // 49
    k_zero_cnt<<<(n + 255) / 256, 256>>>(n);
    k_count<<<(E + 255) / 256, 256>>>(d32, d64, E, n);
    k_dinv<<<(n + 255) / 256, 256>>>(n);
    k_scan_local<<<nb, 1024>>>(n);
    k_scan_bsum<<<1, 64>>>(nb);
    k_scan_add<<<nb, 1024>>>(n);
    k_scatter<<<(E + 255) / 256, 256>>>(s32, s64, d32, d64, E, n);

    // x -> fp16 into g_a16 (runs concurrently-ish after scatter; independent)
    k_x16<<<(MPAD * 32 + 255) / 256, 256>>>(x, n);

    const int mtiles = (n + 127) / 128;  // 391

    // --- layer 1: 256 -> 256 (fp16 x, 2-term fp16 W) ---
    k_split_wt16<<<(256 * 256 + 255) / 256, 256>>>(W1, 256, 256);
    k_gemm_f16<<<dim3(mtiles, 2), 256, SMEM2>>>(n, 256, 256);
    k_agg<256, 8, true><<<(n + 7) / 8, dim3(32, 8)>>>(b1, out, 512, n);

    // --- layer 2: 256 -> 128 (fp16 h1, 2-term fp16 W) ---
    k_split_wt16<<<(128 * 256 + 255) / 256, 256>>>(W2, 256, 128);
    k_gemm_f16<<<dim3(mtiles, 1), 256, SMEM2>>>(n, 256, 128);
    k_agg<128, 16, true><<<(n + 15) / 16, dim3(16, 16)>>>(b2, out + 256, 512, n);

    // --- layer 3: 128 -> 128 (fp16 h2, 2-term fp16 W) ---
    k_split_wt16<<<(128 * 128 + 255) / 256, 256>>>(W3, 128, 128);
    k_gemm_f16<<<dim3(mtiles, 1), 256, SMEM2>>>(n, 128, 128);
    k_agg<128, 16, false><<<(n + 15) / 16, dim3(16, 16)>>>(b3, out + 384, 512, n);
}

// round 11
// speedup vs baseline: 1.7336x; 1.0835x over previous
#include <cuda_runtime.h>
#include <cuda_fp16.h>
#include <cstdint>

// Fixed problem shapes (SimpleGCN): N=50000 nodes, E=800000 edges,
// layers 256->256 (h1), 256->128 (h2), 128->128 (h3), out = [N, 512] fp32.
#define MAXN 50000
#define MAXE 800000
#define MPAD 50048

// ---------------- device scratch (static allocation; no cudaMalloc) --------
__device__ __half g_hh[(size_t)MPAD * 256];   // GEMM output, fp16
__device__ __half g_a16[(size_t)MPAD * 256];  // GEMM A input, fp16 (x16 / agg out)
__device__ __half g_w1h[256 * 256], g_w1l[256 * 256];  // W1^T hi/lo [n][k]
__device__ __half g_w2h[128 * 256], g_w2l[128 * 256];  // W2^T hi/lo
__device__ __half g_w3h[128 * 128], g_w3l[128 * 128];  // W3^T hi/lo
__device__ float g_dinv[MAXN];
__device__ int   g_cnt[MAXN];     // INVARIANT: zero at call entry (restored by scatter)
__device__ int   g_offs[MAXN + 1];
__device__ int   g_bsum[64];
__device__ int   g_esrc[MAXE];
__device__ float g_enorm[MAXE];

// ---------------- edge dtype probe (per-thread, no global flag) --------------
// int64 edge_index (values < 2^31, nonneg) has odd 32-bit words == 0.
// 16 consecutive odd words all zero under int32 random data: ~(2e-5)^16 = never.
__device__ __forceinline__ bool probe64(const int* __restrict__ ei32) {
    int acc = 0;
#pragma unroll
    for (int i = 1; i < 32; i += 2) acc |= ei32[i];
    return acc == 0;
}
__device__ __forceinline__ int load_edge(const int* __restrict__ p32,
                                         const long long* __restrict__ p64,
                                         bool is64, int e, int n) {
    int v = is64 ? (int)p64[e] : p32[e];
    v = v < 0 ? 0 : (v >= n ? n - 1 : v);
    return v;
}

// ---------------- kernel 1: fused prep (count || x->fp16 || W splits) --------
__global__ void k_prep(const float* __restrict__ x,
                       const float* __restrict__ W1,
                       const float* __restrict__ W2,
                       const float* __restrict__ W3,
                       const int* __restrict__ ei32,
                       const long long* __restrict__ ei64, int E, int n) {
    const int CB = (E + 255) >> 8;          // count blocks      (3125)
    const int XB = (MPAD * 32) >> 8;        // x16 blocks        (6256)
    const int W1E = 256 * 256, W2E = 128 * 256, W3E = 128 * 128;
    const int b = blockIdx.x, t = threadIdx.x;

    if (b < CB) {                            // --- degree histogram ---
        int e = b * 256 + t;
        if (e < E) {
            bool is64 = probe64(ei32);
            int d = load_edge(ei32, ei64, is64, E + e, n);  // dst half
            atomicAdd(&g_cnt[d], 1);
        }
    } else if (b < CB + XB) {                // --- x -> fp16 (8 elems/thread) ---
        int i = (b - CB) * 256 + t;
        int row = i >> 5, q = i & 31;
        uint4 hv = make_uint4(0, 0, 0, 0);
        if (row < n) {
            const float* p = &x[(size_t)row * 256 + q * 8];
            float4 f0 = *(const float4*)p;
            float4 f1 = *(const float4*)(p + 4);
            __half2 p0 = __floats2half2_rn(f0.x, f0.y);
            __half2 p1 = __floats2half2_rn(f0.z, f0.w);
            __half2 p2 = __floats2half2_rn(f1.x, f1.y);
            __half2 p3 = __floats2half2_rn(f1.z, f1.w);
            hv.x = *(uint32_t*)&p0; hv.y = *(uint32_t*)&p1;
            hv.z = *(uint32_t*)&p2; hv.w = *(uint32_t*)&p3;
        }
        *(uint4*)&g_a16[(size_t)row * 256 + q * 8] = hv;
    } else {                                 // --- W^T hi/lo splits, 3 layers ---
        int i = (b - CB - XB) * 256 + t;
        const float* W; __half *dh, *dl; int K, N;
        if (i < W1E)             { W = W1; dh = g_w1h; dl = g_w1l; K = 256; N = 256; }
        else if (i < W1E + W2E)  { i -= W1E; W = W2; dh = g_w2h; dl = g_w2l; K = 256; N = 128; }
        else if (i < W1E + W2E + W3E) { i -= W1E + W2E; W = W3; dh = g_w3h; dl = g_w3l; K = 128; N = 128; }
        else return;
        int nn = i / K, kk = i - nn * K;
        float v = W[(size_t)kk * N + nn];
        __half h = __float2half_rn(v);
        __half l = __float2half_rn(v - __half2float(h));
        dh[i] = h;
        dl[i] = l;
    }
}

// ---------------- kernel 2: block scan of degrees + dinv ---------------------
__global__ void k_scan_dinv(int n) {
    __shared__ int ws[32];
    int i = blockIdx.x * 1024 + threadIdx.x;
    int v = (i < n) ? g_cnt[i] : 0;
    if (i < n) g_dinv[i] = rsqrtf((float)(v + 1));  // +1 self-loop

    int lane = threadIdx.x & 31, w = threadIdx.x >> 5;
    int xs = v;
#pragma unroll
    for (int d = 1; d < 32; d <<= 1) {
        int tt = __shfl_up_sync(0xFFFFFFFFu, xs, d);
        if (lane >= d) xs += tt;
    }
    if (lane == 31) ws[w] = xs;
    __syncthreads();
    if (w == 0) {
        int y = ws[lane];
#pragma unroll
        for (int d = 1; d < 32; d <<= 1) {
            int tt = __shfl_up_sync(0xFFFFFFFFu, y, d);
            if (lane >= d) y += tt;
        }
        ws[lane] = y;
    }
    __syncthreads();
    int ex = (w ? ws[w - 1] : 0) + xs - v;          // exclusive within block
    if (i < n) g_offs[i] = ex;
    if (threadIdx.x == 1023) g_bsum[blockIdx.x] = ws[31];  // block total
}

// ---------------- kernel 3: add block prefixes (bsum scan inlined) -----------
__global__ void k_scan_add(int n) {
    __shared__ int sv[64];
    __shared__ int pref;
    int t = threadIdx.x;
    if (t < 64) sv[t] = (t < blockIdx.x) ? g_bsum[t] : 0;
    __syncthreads();
    if (t == 0) {
        int s = 0;
#pragma unroll
        for (int j = 0; j < 64; j++) s += sv[j];
        pref = s;
    }
    __syncthreads();
    int i = blockIdx.x * 1024 + t;
    if (i < n) g_offs[i] += pref;
}

// ---------------- kernel 4: scatter (+ restore g_cnt zero invariant) ---------
// After this, g_offs[d] = END of node d; beg = d ? g_offs[d-1] : 0.
__global__ void k_scatter(const int* __restrict__ ei32,
                          const long long* __restrict__ ei64, int E, int n) {
    int e = blockIdx.x * blockDim.x + threadIdx.x;
    if (e < n) g_cnt[e] = 0;                 // invariant for next call
    if (e >= E) return;
    bool is64 = probe64(ei32);
    int s = load_edge(ei32, ei64, is64, e, n);
    int d = load_edge(ei32, ei64, is64, E + e, n);
    int pos = atomicAdd(&g_offs[d], 1);
    if (pos >= 0 && pos < MAXE) {
        g_esrc[pos]  = s;
        g_enorm[pos] = g_dinv[s] * g_dinv[d];
    }
}

// ---------------- fp16 2-term warp-MMA GEMM (cp.async pipelined) -------------
// C[M,N] = g_a16[M,*256] @ W[K,N]; W^T hi/lo selected by layer (device-side).
#define ROWW 20
#define ARR_B  (128 * ROWW * 4)
#define BUF_B2 (ARR_B * 3)

__device__ __forceinline__ void mma_f16(float* c, uint32_t a0, uint32_t a1,
                                        uint32_t a2, uint32_t a3,
                                        uint32_t b0, uint32_t b1) {
    asm volatile(
        "mma.sync.aligned.m16n8k16.row.col.f32.f16.f16.f32 "
        "{%0,%1,%2,%3}, {%4,%5,%6,%7}, {%8,%9}, {%0,%1,%2,%3};"
        : "+f"(c[0]), "+f"(c[1]), "+f"(c[2]), "+f"(c[3])
        : "r"(a0), "r"(a1), "r"(a2), "r"(a3), "r"(b0), "r"(b1));
}
__device__ __forceinline__ void cp16(uint32_t dst, const void* src) {
    asm volatile("cp.async.cg.shared.global [%0], [%1], 16;"
                 :: "r"(dst), "l"(src));
}
__device__ __forceinline__ uint32_t smem_u32(const void* p) {
    uint32_t a;
    asm("{ .reg .u64 t; cvta.to.shared.u64 t, %1; cvt.u32.u64 %0, t; }"
        : "=r"(a) : "l"(p));
    return a;
}

__global__ void __launch_bounds__(256, 2)
k_gemm_f16(int layer, int M, int K, int N) {
    extern __shared__ char smem[];
    const uint32_t sbase = smem_u32(smem);
    const __half* A  = g_a16;               // device-side binding; lda = 256
    const __half* Bh = (layer == 0) ? g_w1h : (layer == 1) ? g_w2h : g_w3h;
    const __half* Bl = (layer == 0) ? g_w1l : (layer == 1) ? g_w2l : g_w3l;
    const int lda = 256;

    const int tid  = threadIdx.x;
    const int lane = tid & 31;
    const int wid  = tid >> 5;
    const int wm   = wid & 1;
    const int wn   = wid >> 1;
    const int bm   = blockIdx.x * 128;
    const int bn   = blockIdx.y * 128;

    const int l4 = lane >> 2;
    const int l2 = (lane & 3) * 2;

    float acc[4][4][4];
#pragma unroll
    for (int i = 0; i < 4; i++)
#pragma unroll
        for (int j = 0; j < 4; j++)
#pragma unroll
            for (int k = 0; k < 4; k++) acc[i][j][k] = 0.f;

    const int c0r = tid >> 2, c0q = tid & 3;
    const int nStages = K >> 5;

    // A rows bm..bm+127 may exceed M but stay < MPAD (g_a16 padded): safe.
    auto issue = [&](int st, int buf) {
        const int k0 = st << 5;
        const uint32_t db = sbase + buf * BUF_B2;
        const uint32_t w0 = (c0r * ROWW + c0q * 4) * 4;
        const uint32_t w1 = ((c0r + 64) * ROWW + c0q * 4) * 4;
        const size_t a0 = (size_t)(bm + c0r) * lda + k0 + c0q * 8;
        const size_t a1 = (size_t)(bm + c0r + 64) * lda + k0 + c0q * 8;
        cp16(db + w0, A + a0);
        cp16(db + w1, A + a1);
        const size_t g0 = (size_t)(bn + c0r) * K + k0 + c0q * 8;
        const size_t g1 = (size_t)(bn + c0r + 64) * K + k0 + c0q * 8;
        cp16(db + ARR_B + w0, Bh + g0);
        cp16(db + ARR_B + w1, Bh + g1);
        cp16(db + 2 * ARR_B + w0, Bl + g0);
        cp16(db + 2 * ARR_B + w1, Bl + g1);
        asm volatile("cp.async.commit_group;");
    };

    issue(0, 0);

    for (int st = 0; st < nStages; st++) {
        const int buf = st & 1;
        if (st + 1 < nStages) {
            issue(st + 1, buf ^ 1);
            asm volatile("cp.async.wait_group 1;");
        } else {
            asm volatile("cp.async.wait_group 0;");
        }
        __syncthreads();

        const uint32_t* sA  = (const uint32_t*)(smem + buf * BUF_B2);
        const uint32_t* sBh = (const uint32_t*)(smem + buf * BUF_B2 + ARR_B);
        const uint32_t* sBl = (const uint32_t*)(smem + buf * BUF_B2 + 2 * ARR_B);

#pragma unroll
        for (int ks = 0; ks < 2; ks++) {
            const int kwb = ks * 8 + (lane & 3);
            uint32_t bh[4][2], bl[4][2];
#pragma unroll
            for (int nt = 0; nt < 4; nt++) {
                int rw = (wn * 32 + nt * 8 + l4) * ROWW + kwb;
                bh[nt][0] = sBh[rw]; bh[nt][1] = sBh[rw + 4];
                bl[nt][0] = sBl[rw]; bl[nt][1] = sBl[rw + 4];
            }
#pragma unroll
            for (int mt = 0; mt < 4; mt++) {
                int r0 = (wm * 64 + mt * 16 + l4) * ROWW + kwb;
                int r1 = r0 + 8 * ROWW;
                uint32_t a0 = sA[r0], a1 = sA[r1];
                uint32_t a2 = sA[r0 + 4], a3 = sA[r1 + 4];
#pragma unroll
                for (int nt = 0; nt < 4; nt++)
                    mma_f16(acc[mt][nt], a0, a1, a2, a3, bh[nt][0], bh[nt][1]);
#pragma unroll
                for (int nt = 0; nt < 4; nt++)
                    mma_f16(acc[mt][nt], a0, a1, a2, a3, bl[nt][0], bl[nt][1]);
            }
        }
        __syncthreads();
    }

#pragma unroll
    for (int mt = 0; mt < 4; mt++) {
#pragma unroll
        for (int nt = 0; nt < 4; nt++) {
            int row = bm + wm * 64 + mt * 16 + l4;
            int col = bn + wn * 32 + nt * 8 + l2;
            if (row < M)
                *(__half2*)&g_hh[(size_t)row * N + col] =
                    __floats2half2_rn(acc[mt][nt][0], acc[mt][nt][1]);
            if (row + 8 < M)
                *(__half2*)&g_hh[(size_t)(row + 8) * N + col] =
                    __floats2half2_rn(acc[mt][nt][2], acc[mt][nt][3]);
        }
    }
}

// ---------------- aggregation (fp16 gathers) ----------------------------------
__device__ __forceinline__ void unpack8(uint4 v, float* f) {
    float2 a = __half22float2(*(__half2*)&v.x);
    float2 b = __half22float2(*(__half2*)&v.y);
    float2 c = __half22float2(*(__half2*)&v.z);
    float2 d = __half22float2(*(__half2*)&v.w);
    f[0] = a.x; f[1] = a.y; f[2] = b.x; f[3] = b.y;
    f[4] = c.x; f[5] = c.y; f[6] = d.x; f[7] = d.y;
}

// NPB nodes per block; OC/8 threads per node. W16: also write fp16 copy to g_a16.
// g_offs holds END positions (post-scatter); beg = node ? offs[node-1] : 0.
template <int OC, int NPB, bool W16>
__global__ void k_agg(const float* __restrict__ bias,
                      float* __restrict__ out, int ldo, int n) {
    int node = blockIdx.x * NPB + threadIdx.y;
    if (node >= n) return;
    const int colb = threadIdx.x * 8;

    float di = g_dinv[node];
    float s2 = di * di;

    float acc[8], f[8];
    uint4 hs = *(const uint4*)&g_hh[(size_t)node * OC + colb];
    unpack8(hs, f);
#pragma unroll
    for (int j = 0; j < 8; j++) acc[j] = f[j] * s2;

    int beg = node ? g_offs[node - 1] : 0;
    int end = g_offs[node];
    int e = beg;
    for (; e + 1 < end; e += 2) {
        int   s0 = g_esrc[e],  s1 = g_esrc[e + 1];
        float w0 = g_enorm[e], w1 = g_enorm[e + 1];
        uint4 v0 = *(const uint4*)&g_hh[(size_t)s0 * OC + colb];
        uint4 v1 = *(const uint4*)&g_hh[(size_t)s1 * OC + colb];
        float f0[8], f1[8];
        unpack8(v0, f0);
        unpack8(v1, f1);
#pragma unroll
        for (int j = 0; j < 8; j++) acc[j] += f0[j] * w0 + f1[j] * w1;
    }
    if (e < end) {
        int   s = g_esrc[e];
        float w = g_enorm[e];
        uint4 v = *(const uint4*)&g_hh[(size_t)s * OC + colb];
        unpack8(v, f);
#pragma unroll
        for (int j = 0; j < 8; j++) acc[j] += f[j] * w;
    }

    float4 b0 = *(const float4*)&bias[colb];
    float4 b1 = *(const float4*)&bias[colb + 4];
    float r[8];
    r[0] = fmaxf(acc[0] + b0.x, 0.f); r[1] = fmaxf(acc[1] + b0.y, 0.f);
    r[2] = fmaxf(acc[2] + b0.z, 0.f); r[3] = fmaxf(acc[3] + b0.w, 0.f);
    r[4] = fmaxf(acc[4] + b1.x, 0.f); r[5] = fmaxf(acc[5] + b1.y, 0.f);
    r[6] = fmaxf(acc[6] + b1.z, 0.f); r[7] = fmaxf(acc[7] + b1.w, 0.f);

    float* op = &out[(size_t)node * ldo + colb];
    *(float4*)op       = make_float4(r[0], r[1], r[2], r[3]);
    *(float4*)(op + 4) = make_float4(r[4], r[5], r[6], r[7]);

    if (W16) {
        uint4 hv;
        __half2 p0 = __floats2half2_rn(r[0], r[1]);
        __half2 p1 = __floats2half2_rn(r[2], r[3]);
        __half2 p2 = __floats2half2_rn(r[4], r[5]);
        __half2 p3 = __floats2half2_rn(r[6], r[7]);
        hv.x = *(uint32_t*)&p0; hv.y = *(uint32_t*)&p1;
        hv.z = *(uint32_t*)&p2; hv.w = *(uint32_t*)&p3;
        *(uint4*)&g_a16[(size_t)node * 256 + colb] = hv;
    }
}

// ---------------- host launcher ----------------------------------------------
extern "C" void kernel_launch(void* const* d_in, const int* in_sizes, int n_in,
                              void* d_out, int out_size) {
    const float* x  = (const float*)d_in[0];
    const int*       ei32 = (const int*)d_in[1];
    const long long* ei64 = (const long long*)d_in[1];
    const float* W1 = (const float*)d_in[2];
    const float* b1 = (const float*)d_in[3];
    const float* W2 = (const float*)d_in[4];
    const float* b2 = (const float*)d_in[5];
    const float* W3 = (const float*)d_in[6];
    const float* b3 = (const float*)d_in[7];
    float* out = (float*)d_out;

    int n = in_sizes[0] / 256;   // 50000
    int E = in_sizes[1] / 2;     // 800000

    const int SMEM2 = 2 * BUF_B2;  // 61440
    cudaFuncSetAttribute(k_gemm_f16,
                         cudaFuncAttributeMaxDynamicSharedMemorySize, SMEM2);

    // kernel 1: degree count || x->fp16 || W^T splits (independent sections)
    const int CB = (E + 255) / 256;
    const int XB = (MPAD * 32) / 256;
    const int WB = (256 * 256 + 128 * 256 + 128 * 128 + 255) / 256;
    k_prep<<<CB + XB + WB, 256>>>(x, W1, W2, W3, ei32, ei64, E, n);

    int nb = (n + 1023) / 1024;  // 49
    k_scan_dinv<<<nb, 1024>>>(n);
    k_scan_add<<<nb, 1024>>>(n);
    k_scatter<<<CB, 256>>>(ei32, ei64, E, n);

    const int mtiles = (n + 127) / 128;  // 391

    // --- layer 1: 256 -> 256 ---
    k_gemm_f16<<<dim3(mtiles, 2), 256, SMEM2>>>(0, n, 256, 256);
    k_agg<256, 8, true><<<(n + 7) / 8, dim3(32, 8)>>>(b1, out, 512, n);

    // --- layer 2: 256 -> 128 ---
    k_gemm_f16<<<dim3(mtiles, 1), 256, SMEM2>>>(1, n, 256, 128);
    k_agg<128, 16, true><<<(n + 15) / 16, dim3(16, 16)>>>(b2, out + 256, 512, n);

    // --- layer 3: 128 -> 128 ---
    k_gemm_f16<<<dim3(mtiles, 1), 256, SMEM2>>>(2, n, 128, 128);
    k_agg<128, 16, false><<<(n + 15) / 16, dim3(16, 16)>>>(b3, out + 384, 512, n);
}